// round 2
// baseline (speedup 1.0000x reference)
#include <cuda_runtime.h>
#include <cstdint>

#define N_NODES  50000
#define N_EDGES  800000
#define N_GRAPHS 64
#define D_IN     128
#define D_H      256

// ---------------- scratch (no allocations allowed) ----------------
__device__ float g_agg[(size_t)N_NODES * D_H];
__device__ float g_tmp[(size_t)N_NODES * D_H];
__device__ float g_h[(size_t)N_NODES * D_H];
__device__ float g_sums[N_GRAPHS * D_H];
__device__ float g_counts[N_GRAPHS];

// ---------------- zero ----------------
__global__ void zero4_kernel(float4* __restrict__ p, int n4) {
    int i = blockIdx.x * blockDim.x + threadIdx.x;
    if (i < n4) p[i] = make_float4(0.f, 0.f, 0.f, 0.f);
}

// ---------------- edge scatter: agg[dst] += X[src], one warp per edge ----------------
// F = 128 or 256 (floats per node row). Vectorized global reduction (no return).
__global__ void scatter_kernel(const float* __restrict__ X,
                               const int* __restrict__ ei,
                               float* __restrict__ agg, int F) {
    int gt   = blockIdx.x * blockDim.x + threadIdx.x;
    int warp = gt >> 5;
    int lane = gt & 31;
    if (warp >= N_EDGES) return;
    int s = ei[warp];
    int d = ei[N_EDGES + warp];
    const float4* src = (const float4*)(X + (size_t)s * F);
    float4*       dst = (float4*)(agg + (size_t)d * F);
    int nv = F >> 2;  // 32 or 64 float4s per row
    for (int c = lane; c < nv; c += 32) {
        float4 v = src[c];
        asm volatile("red.global.add.v4.f32 [%0], {%1,%2,%3,%4};"
                     :: "l"(dst + c), "f"(v.x), "f"(v.y), "f"(v.z), "f"(v.w)
                     : "memory");
    }
}

// ---------------- SIMT GEMM: C = relu((A [+ A2]) @ B + bias) ----------------
// BM=128, BN=128, BK=16, 256 threads, 8x8 per thread in 2x2 quads of 4x4.
// Requires K % 16 == 0, N % 128 == 0.
template <bool ADD2>
__global__ __launch_bounds__(256, 2)
void gemm_bias_relu(const float* __restrict__ A, const float* __restrict__ A2,
                    const float* __restrict__ B, const float* __restrict__ bias,
                    float* __restrict__ C, int M, int K, int N) {
    constexpr int BM = 128, BN = 128, BK = 16;
    __shared__ float As[BK][BM];
    __shared__ float Bs[BK][BN];

    const int tid  = threadIdx.x;
    const int m0   = blockIdx.x * BM;
    const int n0   = blockIdx.y * BN;
    const int warp = tid >> 5;
    const int lane = tid & 31;
    const int wm   = (warp >> 1) * 32;   // warp row base within tile (0..96)
    const int wn   = (warp & 1) * 64;    // warp col base within tile (0 or 64)
    const int lr   = (lane >> 3) * 4;    // lane row quad (0,4,8,12)
    const int lc   = (lane & 7) * 4;     // lane col quad (0..28)

    float acc[2][4][2][4];
    #pragma unroll
    for (int a = 0; a < 2; a++)
        #pragma unroll
        for (int b = 0; b < 4; b++)
            #pragma unroll
            for (int c = 0; c < 2; c++)
                #pragma unroll
                for (int d = 0; d < 4; d++) acc[a][b][c][d] = 0.f;

    for (int k0 = 0; k0 < K; k0 += BK) {
        // Load A tile (BM x BK = 512 float4), transposed into As[k][m]
        #pragma unroll
        for (int l = 0; l < 2; l++) {
            int idx = tid + l * 256;
            int row = idx >> 2;          // 0..127
            int kc  = (idx & 3) * 4;     // 0,4,8,12
            int gm  = m0 + row;
            float4 v = make_float4(0.f, 0.f, 0.f, 0.f);
            if (gm < M) {
                v = *(const float4*)(A + (size_t)gm * K + k0 + kc);
                if (ADD2) {
                    float4 w = *(const float4*)(A2 + (size_t)gm * K + k0 + kc);
                    v.x += w.x; v.y += w.y; v.z += w.z; v.w += w.w;
                }
            }
            As[kc + 0][row] = v.x;
            As[kc + 1][row] = v.y;
            As[kc + 2][row] = v.z;
            As[kc + 3][row] = v.w;
        }
        // Load B tile (BK x BN = 512 float4)
        #pragma unroll
        for (int l = 0; l < 2; l++) {
            int idx  = tid + l * 256;
            int krow = idx >> 5;         // 0..15
            int col  = (idx & 31) * 4;   // 0..124
            *(float4*)&Bs[krow][col] =
                *(const float4*)(B + (size_t)(k0 + krow) * N + n0 + col);
        }
        __syncthreads();

        #pragma unroll
        for (int kk = 0; kk < BK; kk++) {
            float ra[2][4], rb[2][4];
            *(float4*)ra[0] = *(const float4*)&As[kk][wm + lr];
            *(float4*)ra[1] = *(const float4*)&As[kk][wm + lr + 16];
            *(float4*)rb[0] = *(const float4*)&Bs[kk][wn + lc];
            *(float4*)rb[1] = *(const float4*)&Bs[kk][wn + lc + 32];
            #pragma unroll
            for (int ri = 0; ri < 2; ri++)
                #pragma unroll
                for (int i = 0; i < 4; i++)
                    #pragma unroll
                    for (int cj = 0; cj < 2; cj++)
                        #pragma unroll
                        for (int j = 0; j < 4; j++)
                            acc[ri][i][cj][j] += ra[ri][i] * rb[cj][j];
        }
        __syncthreads();
    }

    // Epilogue: bias + relu + store
    float bb[2][4];
    #pragma unroll
    for (int cj = 0; cj < 2; cj++)
        #pragma unroll
        for (int j = 0; j < 4; j++)
            bb[cj][j] = bias[n0 + wn + lc + cj * 32 + j];

    #pragma unroll
    for (int ri = 0; ri < 2; ri++) {
        #pragma unroll
        for (int i = 0; i < 4; i++) {
            int gm = m0 + wm + lr + ri * 16 + i;
            if (gm < M) {
                #pragma unroll
                for (int cj = 0; cj < 2; cj++) {
                    float4 v;
                    v.x = fmaxf(acc[ri][i][cj][0] + bb[cj][0], 0.f);
                    v.y = fmaxf(acc[ri][i][cj][1] + bb[cj][1], 0.f);
                    v.z = fmaxf(acc[ri][i][cj][2] + bb[cj][2], 0.f);
                    v.w = fmaxf(acc[ri][i][cj][3] + bb[cj][3], 0.f);
                    *(float4*)(C + (size_t)gm * N + n0 + wn + lc + cj * 32) = v;
                }
            }
        }
    }
}

// ---------------- per-graph mean pool (batch sorted -> run-length) ----------------
#define POOL_NPB 128
__global__ void pool_kernel(const float* __restrict__ H,
                            const int* __restrict__ batch,
                            float* __restrict__ sums, float* __restrict__ counts) {
    int f  = threadIdx.x;  // 0..255 feature column
    int n0 = blockIdx.x * POOL_NPB;
    int n1 = n0 + POOL_NPB;
    if (n1 > N_NODES) n1 = N_NODES;
    if (n0 >= N_NODES) return;

    float acc = 0.f;
    int   cur = batch[n0];
    int   runstart = n0;
    for (int n = n0; n < n1; n++) {
        int g = batch[n];
        if (g != cur) {
            atomicAdd(&sums[cur * D_H + f], acc);
            if (f == 0) atomicAdd(&counts[cur], (float)(n - runstart));
            acc = 0.f; cur = g; runstart = n;
        }
        acc += H[(size_t)n * D_H + f];
    }
    atomicAdd(&sums[cur * D_H + f], acc);
    if (f == 0) atomicAdd(&counts[cur], (float)(n1 - runstart));
}

__global__ void div_kernel(const float* __restrict__ sums,
                           const float* __restrict__ counts,
                           float* __restrict__ out) {
    int i = blockIdx.x * blockDim.x + threadIdx.x;
    if (i < N_GRAPHS * D_H) out[i] = sums[i] / fmaxf(counts[i >> 8], 1.f);
}

// ---------------- launch ----------------
extern "C" void kernel_launch(void* const* d_in, const int* in_sizes, int n_in,
                              void* d_out, int out_size) {
    const float* x     = (const float*)d_in[0];
    const int*   ei    = (const int*)d_in[1];    // JAX x64 disabled -> int32
    const int*   batch = (const int*)d_in[2];    // int32
    const float* W1_0 = (const float*)d_in[3];
    const float* b1_0 = (const float*)d_in[4];
    const float* W2_0 = (const float*)d_in[5];
    const float* b2_0 = (const float*)d_in[6];
    const float* W1_1 = (const float*)d_in[7];
    const float* b1_1 = (const float*)d_in[8];
    const float* W2_1 = (const float*)d_in[9];
    const float* b2_1 = (const float*)d_in[10];
    float* out = (float*)d_out;

    float *agg, *tmp, *h, *sums, *counts;
    cudaGetSymbolAddress((void**)&agg,    g_agg);
    cudaGetSymbolAddress((void**)&tmp,    g_tmp);
    cudaGetSymbolAddress((void**)&h,      g_h);
    cudaGetSymbolAddress((void**)&sums,   g_sums);
    cudaGetSymbolAddress((void**)&counts, g_counts);

    const dim3 gemm_grid((N_NODES + 127) / 128, D_H / 128);
    const int scatter_blocks = (N_EDGES * 32 + 255) / 256;

    // ---- layer 0 ----
    {
        int n4 = N_NODES * D_IN / 4;
        zero4_kernel<<<(n4 + 255) / 256, 256>>>((float4*)agg, n4);
    }
    scatter_kernel<<<scatter_blocks, 256>>>(x, ei, agg, D_IN);
    gemm_bias_relu<true ><<<gemm_grid, 256>>>(x,  agg, W1_0, b1_0, tmp, N_NODES, D_IN, D_H);
    gemm_bias_relu<false><<<gemm_grid, 256>>>(tmp, nullptr, W2_0, b2_0, h, N_NODES, D_H, D_H);

    // ---- layer 1 ----
    {
        int n4 = N_NODES * D_H / 4;
        zero4_kernel<<<(n4 + 255) / 256, 256>>>((float4*)agg, n4);
    }
    scatter_kernel<<<scatter_blocks, 256>>>(h, ei, agg, D_H);
    gemm_bias_relu<true ><<<gemm_grid, 256>>>(h,  agg, W1_1, b1_1, tmp, N_NODES, D_H, D_H);
    gemm_bias_relu<false><<<gemm_grid, 256>>>(tmp, nullptr, W2_1, b2_1, h, N_NODES, D_H, D_H);

    // ---- pool ----
    {
        int ns4 = N_GRAPHS * D_H / 4;
        zero4_kernel<<<(ns4 + 255) / 256, 256>>>((float4*)sums, ns4);
        int nc4 = N_GRAPHS / 4;
        zero4_kernel<<<1, 32>>>((float4*)counts, nc4);
    }
    pool_kernel<<<(N_NODES + POOL_NPB - 1) / POOL_NPB, 256>>>(h, batch, sums, counts);
    div_kernel<<<(N_GRAPHS * D_H + 255) / 256, 256>>>(sums, counts, out);
}

// round 3
// speedup vs baseline: 1.0470x; 1.0470x over previous
#include <cuda_runtime.h>
#include <cstdint>

#define N_NODES  50000
#define N_EDGES  800000
#define N_GRAPHS 64
#define D_IN     128
#define D_H      256

// ---------------- scratch (no allocations allowed) ----------------
__device__ float g_agg[(size_t)N_NODES * D_H];
__device__ float g_tmp[(size_t)N_NODES * D_H];
__device__ float g_h[(size_t)N_NODES * D_H];
__device__ float g_sums[N_GRAPHS * D_H];
__device__ float g_counts[N_GRAPHS];

// ---------------- zero ----------------
__global__ void zero4_kernel(float4* __restrict__ p, int n4) {
    int i = blockIdx.x * blockDim.x + threadIdx.x;
    if (i < n4) p[i] = make_float4(0.f, 0.f, 0.f, 0.f);
}

// ---------------- edge scatter: agg[dst] += X[src], one warp per edge ----------------
__global__ void scatter_kernel(const float* __restrict__ X,
                               const int* __restrict__ ei,
                               float* __restrict__ agg, int F) {
    int gt   = blockIdx.x * blockDim.x + threadIdx.x;
    int warp = gt >> 5;
    int lane = gt & 31;
    if (warp >= N_EDGES) return;
    int s = ei[warp];
    int d = ei[N_EDGES + warp];
    const float4* src = (const float4*)(X + (size_t)s * F);
    float4*       dst = (float4*)(agg + (size_t)d * F);
    int nv = F >> 2;
    for (int c = lane; c < nv; c += 32) {
        float4 v = src[c];
        asm volatile("red.global.add.v4.f32 [%0], {%1,%2,%3,%4};"
                     :: "l"(dst + c), "f"(v.x), "f"(v.y), "f"(v.z), "f"(v.w)
                     : "memory");
    }
}

// ---------------- SIMT GEMM with packed fma.rn.f32x2 ----------------
// C = relu((A [+ A2]) @ B + bias).  BM=128, BN=128, BK=16, 256 threads,
// 8x8 per thread (stored as 8 rows x 4 f32x2 column-pairs).
// Requires K % 16 == 0, N % 128 == 0.
template <bool ADD2>
__global__ __launch_bounds__(256, 2)
void gemm_bias_relu(const float* __restrict__ A, const float* __restrict__ A2,
                    const float* __restrict__ B, const float* __restrict__ bias,
                    float* __restrict__ C, int M, int K, int N) {
    constexpr int BM = 128, BN = 128, BK = 16;
    __shared__ float As[BK][BM + 4];
    __shared__ float Bs[BK][BN + 4];

    const int tid  = threadIdx.x;
    const int m0   = blockIdx.x * BM;
    const int n0   = blockIdx.y * BN;
    const int warp = tid >> 5;
    const int lane = tid & 31;
    const int wm   = (warp >> 1) * 32;   // warp row base (0..96)
    const int wn   = (warp & 1) * 64;    // warp col base (0 or 64)
    const int lr   = (lane >> 3) * 4;    // lane row quad (0,4,8,12)
    const int lc   = (lane & 7) * 4;     // lane col quad (0..28)

    // acc2[ri][i][cj][p] holds column pair (2p, 2p+1) of quad cj for row i of half ri
    unsigned long long acc2[2][4][2][2];
    #pragma unroll
    for (int a = 0; a < 2; a++)
        #pragma unroll
        for (int b = 0; b < 4; b++)
            #pragma unroll
            for (int c = 0; c < 2; c++)
                #pragma unroll
                for (int d = 0; d < 2; d++) acc2[a][b][c][d] = 0ULL;

    for (int k0 = 0; k0 < K; k0 += BK) {
        // Load A tile (BM x BK), transposed into As[k][m]
        #pragma unroll
        for (int l = 0; l < 2; l++) {
            int idx = tid + l * 256;
            int row = idx >> 2;
            int kc  = (idx & 3) * 4;
            int gm  = m0 + row;
            float4 v = make_float4(0.f, 0.f, 0.f, 0.f);
            if (gm < M) {
                v = *(const float4*)(A + (size_t)gm * K + k0 + kc);
                if (ADD2) {
                    float4 w = *(const float4*)(A2 + (size_t)gm * K + k0 + kc);
                    v.x += w.x; v.y += w.y; v.z += w.z; v.w += w.w;
                }
            }
            As[kc + 0][row] = v.x;
            As[kc + 1][row] = v.y;
            As[kc + 2][row] = v.z;
            As[kc + 3][row] = v.w;
        }
        // Load B tile (BK x BN)
        #pragma unroll
        for (int l = 0; l < 2; l++) {
            int idx  = tid + l * 256;
            int krow = idx >> 5;
            int col  = (idx & 31) * 4;
            *(float4*)&Bs[krow][col] =
                *(const float4*)(B + (size_t)(k0 + krow) * N + n0 + col);
        }
        __syncthreads();

        #pragma unroll
        for (int kk = 0; kk < BK; kk++) {
            float ra[2][4];
            *(float4*)ra[0] = *(const float4*)&As[kk][wm + lr];
            *(float4*)ra[1] = *(const float4*)&As[kk][wm + lr + 16];
            // B columns as packed f32x2 pairs straight out of LDS.128
            ulonglong2 rb0 = *(const ulonglong2*)&Bs[kk][wn + lc];
            ulonglong2 rb1 = *(const ulonglong2*)&Bs[kk][wn + lc + 32];
            unsigned long long b2[2][2] = {{rb0.x, rb0.y}, {rb1.x, rb1.y}};

            #pragma unroll
            for (int ri = 0; ri < 2; ri++) {
                #pragma unroll
                for (int i = 0; i < 4; i++) {
                    unsigned long long a2;
                    asm("mov.b64 %0, {%1, %1};"
                        : "=l"(a2) : "r"(__float_as_uint(ra[ri][i])));
                    #pragma unroll
                    for (int cj = 0; cj < 2; cj++)
                        #pragma unroll
                        for (int p = 0; p < 2; p++)
                            asm("fma.rn.f32x2 %0, %1, %2, %0;"
                                : "+l"(acc2[ri][i][cj][p])
                                : "l"(a2), "l"(b2[cj][p]));
                }
            }
        }
        __syncthreads();
    }

    // Epilogue: bias + relu + store
    float bb[2][4];
    #pragma unroll
    for (int cj = 0; cj < 2; cj++)
        #pragma unroll
        for (int j = 0; j < 4; j++)
            bb[cj][j] = bias[n0 + wn + lc + cj * 32 + j];

    #pragma unroll
    for (int ri = 0; ri < 2; ri++) {
        #pragma unroll
        for (int i = 0; i < 4; i++) {
            int gm = m0 + wm + lr + ri * 16 + i;
            if (gm < M) {
                #pragma unroll
                for (int cj = 0; cj < 2; cj++) {
                    uint2 p0 = *(uint2*)&acc2[ri][i][cj][0];
                    uint2 p1 = *(uint2*)&acc2[ri][i][cj][1];
                    float4 v;
                    v.x = fmaxf(__uint_as_float(p0.x) + bb[cj][0], 0.f);
                    v.y = fmaxf(__uint_as_float(p0.y) + bb[cj][1], 0.f);
                    v.z = fmaxf(__uint_as_float(p1.x) + bb[cj][2], 0.f);
                    v.w = fmaxf(__uint_as_float(p1.y) + bb[cj][3], 0.f);
                    *(float4*)(C + (size_t)gm * N + n0 + wn + lc + cj * 32) = v;
                }
            }
        }
    }
}

// ---------------- per-graph mean pool (batch sorted -> run-length) ----------------
#define POOL_NPB 128
__global__ void pool_kernel(const float* __restrict__ H,
                            const int* __restrict__ batch,
                            float* __restrict__ sums, float* __restrict__ counts) {
    int f  = threadIdx.x;
    int n0 = blockIdx.x * POOL_NPB;
    int n1 = n0 + POOL_NPB;
    if (n1 > N_NODES) n1 = N_NODES;
    if (n0 >= N_NODES) return;

    float acc = 0.f;
    int   cur = batch[n0];
    int   runstart = n0;
    for (int n = n0; n < n1; n++) {
        int g = batch[n];
        if (g != cur) {
            atomicAdd(&sums[cur * D_H + f], acc);
            if (f == 0) atomicAdd(&counts[cur], (float)(n - runstart));
            acc = 0.f; cur = g; runstart = n;
        }
        acc += H[(size_t)n * D_H + f];
    }
    atomicAdd(&sums[cur * D_H + f], acc);
    if (f == 0) atomicAdd(&counts[cur], (float)(n1 - runstart));
}

__global__ void div_kernel(const float* __restrict__ sums,
                           const float* __restrict__ counts,
                           float* __restrict__ out) {
    int i = blockIdx.x * blockDim.x + threadIdx.x;
    if (i < N_GRAPHS * D_H) out[i] = sums[i] / fmaxf(counts[i >> 8], 1.f);
}

// ---------------- launch ----------------
extern "C" void kernel_launch(void* const* d_in, const int* in_sizes, int n_in,
                              void* d_out, int out_size) {
    const float* x     = (const float*)d_in[0];
    const int*   ei    = (const int*)d_in[1];    // int32 (JAX x64 disabled)
    const int*   batch = (const int*)d_in[2];
    const float* W1_0 = (const float*)d_in[3];
    const float* b1_0 = (const float*)d_in[4];
    const float* W2_0 = (const float*)d_in[5];
    const float* b2_0 = (const float*)d_in[6];
    const float* W1_1 = (const float*)d_in[7];
    const float* b1_1 = (const float*)d_in[8];
    const float* W2_1 = (const float*)d_in[9];
    const float* b2_1 = (const float*)d_in[10];
    float* out = (float*)d_out;

    float *agg, *tmp, *h, *sums, *counts;
    cudaGetSymbolAddress((void**)&agg,    g_agg);
    cudaGetSymbolAddress((void**)&tmp,    g_tmp);
    cudaGetSymbolAddress((void**)&h,      g_h);
    cudaGetSymbolAddress((void**)&sums,   g_sums);
    cudaGetSymbolAddress((void**)&counts, g_counts);

    const dim3 gemm_grid((N_NODES + 127) / 128, D_H / 128);
    const int scatter_blocks = (N_EDGES * 32 + 255) / 256;

    // ---- layer 0 ----
    {
        int n4 = N_NODES * D_IN / 4;
        zero4_kernel<<<(n4 + 255) / 256, 256>>>((float4*)agg, n4);
    }
    scatter_kernel<<<scatter_blocks, 256>>>(x, ei, agg, D_IN);
    gemm_bias_relu<true ><<<gemm_grid, 256>>>(x,  agg, W1_0, b1_0, tmp, N_NODES, D_IN, D_H);
    gemm_bias_relu<false><<<gemm_grid, 256>>>(tmp, nullptr, W2_0, b2_0, h, N_NODES, D_H, D_H);

    // ---- layer 1 ----
    {
        int n4 = N_NODES * D_H / 4;
        zero4_kernel<<<(n4 + 255) / 256, 256>>>((float4*)agg, n4);
    }
    scatter_kernel<<<scatter_blocks, 256>>>(h, ei, agg, D_H);
    gemm_bias_relu<true ><<<gemm_grid, 256>>>(h,  agg, W1_1, b1_1, tmp, N_NODES, D_H, D_H);
    gemm_bias_relu<false><<<gemm_grid, 256>>>(tmp, nullptr, W2_1, b2_1, h, N_NODES, D_H, D_H);

    // ---- pool ----
    {
        int ns4 = N_GRAPHS * D_H / 4;
        zero4_kernel<<<(ns4 + 255) / 256, 256>>>((float4*)sums, ns4);
        zero4_kernel<<<1, 32>>>((float4*)counts, N_GRAPHS / 4);
    }
    pool_kernel<<<(N_NODES + POOL_NPB - 1) / POOL_NPB, 256>>>(h, batch, sums, counts);
    div_kernel<<<(N_GRAPHS * D_H + 255) / 256, 256>>>(sums, counts, out);
}

// round 5
// speedup vs baseline: 2.3387x; 2.2336x over previous
#include <cuda_runtime.h>
#include <cuda_bf16.h>
#include <cstdint>

#define N_NODES  50000
#define N_EDGES  800000
#define N_GRAPHS 64
#define D_IN     128
#define D_H      256

// ==================== scratch (no allocations allowed) ====================
__device__ float g_h[(size_t)N_NODES * D_H];                 // fp32 activations
__device__ __nv_bfloat16 g_ah[(size_t)N_NODES * D_H];        // split activations (GEMM A)
__device__ __nv_bfloat16 g_al[(size_t)N_NODES * D_H];
__device__ __nv_bfloat16 g_th[(size_t)N_NODES * D_H];        // inter-GEMM split
__device__ __nv_bfloat16 g_tl[(size_t)N_NODES * D_H];
__device__ __nv_bfloat16 g_wh[4][D_H * D_H];
__device__ __nv_bfloat16 g_wl[4][D_H * D_H];
__device__ int g_deg[N_NODES];
__device__ int g_offs[N_NODES + 1];
__device__ int g_cursor[N_NODES];
__device__ int g_csr[N_EDGES];
__device__ float g_sums[N_GRAPHS * D_H];
__device__ float g_counts[N_GRAPHS];

// ==================== small kernels ====================
__global__ void zero4_kernel(float4* __restrict__ p, int n4) {
    int i = blockIdx.x * blockDim.x + threadIdx.x;
    if (i < n4) p[i] = make_float4(0.f, 0.f, 0.f, 0.f);
}

// W[K][N] fp32 -> WhT/WlT[N][K] bf16 (hi/lo split, transposed)
__global__ void prep_w_kernel(const float* __restrict__ W,
                              __nv_bfloat16* __restrict__ WhT,
                              __nv_bfloat16* __restrict__ WlT, int K, int N) {
    int idx = blockIdx.x * blockDim.x + threadIdx.x;
    if (idx >= K * N) return;
    int k = idx / N, n = idx % N;
    float w = W[idx];
    __nv_bfloat16 h = __float2bfloat16(w);
    __nv_bfloat16 l = __float2bfloat16(w - __bfloat162float(h));
    WhT[(size_t)n * K + k] = h;
    WlT[(size_t)n * K + k] = l;
}

// ==================== CSR build ====================
__global__ void hist_kernel(const int* __restrict__ ei, int* __restrict__ deg) {
    int e = blockIdx.x * blockDim.x + threadIdx.x;
    if (e < N_EDGES) atomicAdd(&deg[ei[N_EDGES + e]], 1);
}

__global__ void scan_kernel(const int* __restrict__ deg, int* __restrict__ offs,
                            int* __restrict__ cursor) {
    __shared__ int swarp[32];
    __shared__ int carry;
    int tid = threadIdx.x;
    int lane = tid & 31, w = tid >> 5;
    if (tid == 0) { carry = 0; offs[0] = 0; }
    __syncthreads();
    for (int base = 0; base < N_NODES; base += 1024) {
        int i = base + tid;
        int v = (i < N_NODES) ? deg[i] : 0;
        int s = v;
        #pragma unroll
        for (int d = 1; d < 32; d <<= 1) {
            int t = __shfl_up_sync(0xffffffffu, s, d);
            if (lane >= d) s += t;
        }
        if (lane == 31) swarp[w] = s;
        __syncthreads();
        if (w == 0) {
            int ss = swarp[lane];
            #pragma unroll
            for (int d = 1; d < 32; d <<= 1) {
                int u = __shfl_up_sync(0xffffffffu, ss, d);
                if (lane >= d) ss += u;
            }
            swarp[lane] = ss;
        }
        __syncthreads();
        int incl = s + (w > 0 ? swarp[w - 1] : 0) + carry;
        if (i < N_NODES) {
            offs[i + 1] = incl;
            cursor[i] = incl - v;
        }
        __syncthreads();
        if (tid == 1023) carry = incl;
        __syncthreads();
    }
}

__global__ void fill_kernel(const int* __restrict__ ei, int* __restrict__ cursor,
                            int* __restrict__ csr) {
    int e = blockIdx.x * blockDim.x + threadIdx.x;
    if (e < N_EDGES) {
        int pos = atomicAdd(&cursor[ei[N_EDGES + e]], 1);
        csr[pos] = ei[e];
    }
}

// ==================== gather + self-add + bf16 split ====================
// out(node) = X[node] + sum_{s in nbrs(node)} X[s], written as bf16 hi/lo pair.
// One warp per node. F = 128 or 256 (floats per row).
template <int F>
__global__ void gather_split(const float* __restrict__ X,
                             const int* __restrict__ offs,
                             const int* __restrict__ csr,
                             __nv_bfloat16* __restrict__ Ah,
                             __nv_bfloat16* __restrict__ Al) {
    int warp = (blockIdx.x * blockDim.x + threadIdx.x) >> 5;
    int lane = threadIdx.x & 31;
    if (warp >= N_NODES) return;
    constexpr int C = F / 128;           // float4 per lane (1 or 2)
    float4 acc[C];
    const float4* xs = (const float4*)(X + (size_t)warp * F);
    #pragma unroll
    for (int c = 0; c < C; c++) acc[c] = xs[lane + c * 32];
    int beg = offs[warp], end = offs[warp + 1];
    for (int e = beg; e < end; e++) {
        int s = csr[e];
        const float4* r = (const float4*)(X + (size_t)s * F);
        #pragma unroll
        for (int c = 0; c < C; c++) {
            float4 v = r[lane + c * 32];
            acc[c].x += v.x; acc[c].y += v.y; acc[c].z += v.z; acc[c].w += v.w;
        }
    }
    #pragma unroll
    for (int c = 0; c < C; c++) {
        float vv[4] = {acc[c].x, acc[c].y, acc[c].z, acc[c].w};
        uint32_t hp[2], lp[2];
        #pragma unroll
        for (int e = 0; e < 2; e++) {
            __nv_bfloat16 h0 = __float2bfloat16(vv[2 * e]);
            __nv_bfloat16 h1 = __float2bfloat16(vv[2 * e + 1]);
            __nv_bfloat16 l0 = __float2bfloat16(vv[2 * e] - __bfloat162float(h0));
            __nv_bfloat16 l1 = __float2bfloat16(vv[2 * e + 1] - __bfloat162float(h1));
            hp[e] = (uint32_t)*(unsigned short*)&h0 | ((uint32_t)*(unsigned short*)&h1 << 16);
            lp[e] = (uint32_t)*(unsigned short*)&l0 | ((uint32_t)*(unsigned short*)&l1 << 16);
        }
        size_t o = (size_t)warp * F + (lane + c * 32) * 4;
        *(uint2*)(Ah + o) = make_uint2(hp[0], hp[1]);
        *(uint2*)(Al + o) = make_uint2(lp[0], lp[1]);
    }
}

// ==================== mma.sync bf16 split-GEMM ====================
// C = relu((Ah+Al) @ (Bh+Bl)^T + bias), 3 HMMA terms (hh, hl, lh).
// Block 128x128, 8 warps (4 m x 2 n), warp tile 32x64, BK=64.
// SMEM rows padded to stride 72 bf16 -> conflict-free fragment loads.
#define GSW 72
#define GEMM_SMEM (4 * 128 * GSW * 2)

__device__ __forceinline__ void mma16816(float* d, const uint32_t* a, const uint32_t* b) {
    asm volatile(
        "mma.sync.aligned.m16n8k16.row.col.f32.bf16.bf16.f32 "
        "{%0,%1,%2,%3}, {%4,%5,%6,%7}, {%8,%9}, {%0,%1,%2,%3};"
        : "+f"(d[0]), "+f"(d[1]), "+f"(d[2]), "+f"(d[3])
        : "r"(a[0]), "r"(a[1]), "r"(a[2]), "r"(a[3]), "r"(b[0]), "r"(b[1]));
}

template <bool OUT_F32>
__global__ void __launch_bounds__(256, 2)
gemm_mma(const __nv_bfloat16* __restrict__ Ahg, const __nv_bfloat16* __restrict__ Alg,
         const __nv_bfloat16* __restrict__ BhT, const __nv_bfloat16* __restrict__ BlT,
         const float* __restrict__ bias,
         float* __restrict__ Cf, __nv_bfloat16* __restrict__ Ch,
         __nv_bfloat16* __restrict__ Cl, int M, int K) {
    extern __shared__ __nv_bfloat16 smem[];
    __nv_bfloat16* sAh = smem;
    __nv_bfloat16* sAl = smem + 128 * GSW;
    __nv_bfloat16* sBh = smem + 2 * 128 * GSW;
    __nv_bfloat16* sBl = smem + 3 * 128 * GSW;

    const int tid  = threadIdx.x;
    const int wid  = tid >> 5;
    const int lane = tid & 31;
    const int m0   = blockIdx.x * 128;
    const int n0   = blockIdx.y * 128;
    const int wm   = (wid & 3) * 32;
    const int wn   = (wid >> 2) * 64;
    const int fr   = lane >> 2;        // fragment row / B col group
    const int fc   = (lane & 3) * 2;   // fragment k offset

    float acc[2][8][4];
    #pragma unroll
    for (int a = 0; a < 2; a++)
        #pragma unroll
        for (int b = 0; b < 8; b++)
            #pragma unroll
            for (int c = 0; c < 4; c++) acc[a][b][c] = 0.f;

    for (int k0 = 0; k0 < K; k0 += 64) {
        // ---- load tiles: each thread 4 uint4 per array ----
        #pragma unroll
        for (int it = 0; it < 4; it++) {
            int idx = tid + it * 256;
            int row = idx >> 3;
            int q   = idx & 7;
            int so  = row * GSW + q * 8;
            uint4 vh = make_uint4(0, 0, 0, 0), vl = make_uint4(0, 0, 0, 0);
            if (m0 + row < M) {
                size_t g = (size_t)(m0 + row) * K + k0 + q * 8;
                vh = *(const uint4*)(Ahg + g);
                vl = *(const uint4*)(Alg + g);
            }
            *(uint4*)(sAh + so) = vh;
            *(uint4*)(sAl + so) = vl;
            size_t gb = (size_t)(n0 + row) * K + k0 + q * 8;
            *(uint4*)(sBh + so) = *(const uint4*)(BhT + gb);
            *(uint4*)(sBl + so) = *(const uint4*)(BlT + gb);
        }
        __syncthreads();

        #pragma unroll
        for (int kk = 0; kk < 64; kk += 16) {
            // A fragments (hi & lo) for 2 m-tiles
            uint32_t ah[2][4], al[2][4];
            #pragma unroll
            for (int mt = 0; mt < 2; mt++) {
                int base = wm + mt * 16;
                int o0 = (base + fr) * GSW + kk + fc;
                int o1 = (base + fr + 8) * GSW + kk + fc;
                ah[mt][0] = *(const uint32_t*)(sAh + o0);
                ah[mt][1] = *(const uint32_t*)(sAh + o1);
                ah[mt][2] = *(const uint32_t*)(sAh + o0 + 8);
                ah[mt][3] = *(const uint32_t*)(sAh + o1 + 8);
                al[mt][0] = *(const uint32_t*)(sAl + o0);
                al[mt][1] = *(const uint32_t*)(sAl + o1);
                al[mt][2] = *(const uint32_t*)(sAl + o0 + 8);
                al[mt][3] = *(const uint32_t*)(sAl + o1 + 8);
            }
            #pragma unroll
            for (int nt = 0; nt < 8; nt++) {
                int ob = (wn + nt * 8 + fr) * GSW + kk + fc;
                uint32_t bh[2], bl[2];
                bh[0] = *(const uint32_t*)(sBh + ob);
                bh[1] = *(const uint32_t*)(sBh + ob + 8);
                bl[0] = *(const uint32_t*)(sBl + ob);
                bl[1] = *(const uint32_t*)(sBl + ob + 8);
                #pragma unroll
                for (int mt = 0; mt < 2; mt++) {
                    mma16816(acc[mt][nt], ah[mt], bh);
                    mma16816(acc[mt][nt], ah[mt], bl);
                    mma16816(acc[mt][nt], al[mt], bh);
                }
            }
        }
        __syncthreads();
    }

    // ---- epilogue: bias + relu ----
    #pragma unroll
    for (int mt = 0; mt < 2; mt++) {
        int gr0 = m0 + wm + mt * 16 + fr;
        int gr1 = gr0 + 8;
        #pragma unroll
        for (int nt = 0; nt < 8; nt++) {
            int col = n0 + wn + nt * 8 + fc;
            float b0 = bias[col], b1 = bias[col + 1];
            float v00 = fmaxf(acc[mt][nt][0] + b0, 0.f);
            float v01 = fmaxf(acc[mt][nt][1] + b1, 0.f);
            float v10 = fmaxf(acc[mt][nt][2] + b0, 0.f);
            float v11 = fmaxf(acc[mt][nt][3] + b1, 0.f);
            if (OUT_F32) {
                if (gr0 < M) *(float2*)(Cf + (size_t)gr0 * 256 + col) = make_float2(v00, v01);
                if (gr1 < M) *(float2*)(Cf + (size_t)gr1 * 256 + col) = make_float2(v10, v11);
            } else {
                __nv_bfloat16 h0, h1, l0, l1;
                if (gr0 < M) {
                    h0 = __float2bfloat16(v00); h1 = __float2bfloat16(v01);
                    l0 = __float2bfloat16(v00 - __bfloat162float(h0));
                    l1 = __float2bfloat16(v01 - __bfloat162float(h1));
                    uint32_t ph = (uint32_t)*(unsigned short*)&h0 | ((uint32_t)*(unsigned short*)&h1 << 16);
                    uint32_t pl = (uint32_t)*(unsigned short*)&l0 | ((uint32_t)*(unsigned short*)&l1 << 16);
                    *(uint32_t*)(Ch + (size_t)gr0 * 256 + col) = ph;
                    *(uint32_t*)(Cl + (size_t)gr0 * 256 + col) = pl;
                }
                if (gr1 < M) {
                    h0 = __float2bfloat16(v10); h1 = __float2bfloat16(v11);
                    l0 = __float2bfloat16(v10 - __bfloat162float(h0));
                    l1 = __float2bfloat16(v11 - __bfloat162float(h1));
                    uint32_t ph = (uint32_t)*(unsigned short*)&h0 | ((uint32_t)*(unsigned short*)&h1 << 16);
                    uint32_t pl = (uint32_t)*(unsigned short*)&l0 | ((uint32_t)*(unsigned short*)&l1 << 16);
                    *(uint32_t*)(Ch + (size_t)gr1 * 256 + col) = ph;
                    *(uint32_t*)(Cl + (size_t)gr1 * 256 + col) = pl;
                }
            }
        }
    }
}

// ==================== pool ====================
#define POOL_NPB 128
__global__ void pool_kernel(const float* __restrict__ H,
                            const int* __restrict__ batch,
                            float* __restrict__ sums, float* __restrict__ counts) {
    int f  = threadIdx.x;
    int n0 = blockIdx.x * POOL_NPB;
    int n1 = n0 + POOL_NPB;
    if (n1 > N_NODES) n1 = N_NODES;
    if (n0 >= N_NODES) return;

    float acc = 0.f;
    int cur = batch[n0];
    int runstart = n0;
    for (int n = n0; n < n1; n++) {
        int g = batch[n];
        if (g != cur) {
            atomicAdd(&sums[cur * D_H + f], acc);
            if (f == 0) atomicAdd(&counts[cur], (float)(n - runstart));
            acc = 0.f; cur = g; runstart = n;
        }
        acc += H[(size_t)n * D_H + f];
    }
    atomicAdd(&sums[cur * D_H + f], acc);
    if (f == 0) atomicAdd(&counts[cur], (float)(n1 - runstart));
}

__global__ void div_kernel(const float* __restrict__ sums,
                           const float* __restrict__ counts,
                           float* __restrict__ out) {
    int i = blockIdx.x * blockDim.x + threadIdx.x;
    if (i < N_GRAPHS * D_H) out[i] = sums[i] / fmaxf(counts[i >> 8], 1.f);
}

// ==================== launch ====================
extern "C" void kernel_launch(void* const* d_in, const int* in_sizes, int n_in,
                              void* d_out, int out_size) {
    const float* x     = (const float*)d_in[0];
    const int*   ei    = (const int*)d_in[1];
    const int*   batch = (const int*)d_in[2];
    const float* W1_0 = (const float*)d_in[3];
    const float* b1_0 = (const float*)d_in[4];
    const float* W2_0 = (const float*)d_in[5];
    const float* b2_0 = (const float*)d_in[6];
    const float* W1_1 = (const float*)d_in[7];
    const float* b1_1 = (const float*)d_in[8];
    const float* W2_1 = (const float*)d_in[9];
    const float* b2_1 = (const float*)d_in[10];
    float* out = (float*)d_out;

    float *h, *sums, *counts;
    __nv_bfloat16 *ah, *al, *th, *tl, *wh, *wl;
    int *deg, *offs, *cursor, *csr;
    cudaGetSymbolAddress((void**)&h,      g_h);
    cudaGetSymbolAddress((void**)&ah,     g_ah);
    cudaGetSymbolAddress((void**)&al,     g_al);
    cudaGetSymbolAddress((void**)&th,     g_th);
    cudaGetSymbolAddress((void**)&tl,     g_tl);
    cudaGetSymbolAddress((void**)&wh,     g_wh);
    cudaGetSymbolAddress((void**)&wl,     g_wl);
    cudaGetSymbolAddress((void**)&deg,    g_deg);
    cudaGetSymbolAddress((void**)&offs,   g_offs);
    cudaGetSymbolAddress((void**)&cursor, g_cursor);
    cudaGetSymbolAddress((void**)&csr,    g_csr);
    cudaGetSymbolAddress((void**)&sums,   g_sums);
    cudaGetSymbolAddress((void**)&counts, g_counts);
    __nv_bfloat16* wh0 = wh;                 __nv_bfloat16* wl0 = wl;
    __nv_bfloat16* wh1 = wh + D_H * D_H;     __nv_bfloat16* wl1 = wl + D_H * D_H;
    __nv_bfloat16* wh2 = wh + 2 * D_H * D_H; __nv_bfloat16* wl2 = wl + 2 * D_H * D_H;
    __nv_bfloat16* wh3 = wh + 3 * D_H * D_H; __nv_bfloat16* wl3 = wl + 3 * D_H * D_H;

    cudaFuncSetAttribute(gemm_mma<false>, cudaFuncAttributeMaxDynamicSharedMemorySize, GEMM_SMEM);
    cudaFuncSetAttribute(gemm_mma<true >, cudaFuncAttributeMaxDynamicSharedMemorySize, GEMM_SMEM);

    const dim3 gemm_grid((N_NODES + 127) / 128, 2);
    const int  edge_blocks = (N_EDGES + 255) / 256;
    const int  node_warp_blocks = (N_NODES * 32 + 255) / 256;

    // ---- weight prep (tiny) + CSR build (once) ----
    prep_w_kernel<<<(D_IN * D_H + 255) / 256, 256>>>(W1_0, wh0, wl0, D_IN, D_H);
    prep_w_kernel<<<(D_H * D_H + 255) / 256, 256>>>(W2_0, wh1, wl1, D_H, D_H);
    prep_w_kernel<<<(D_H * D_H + 255) / 256, 256>>>(W1_1, wh2, wl2, D_H, D_H);
    prep_w_kernel<<<(D_H * D_H + 255) / 256, 256>>>(W2_1, wh3, wl3, D_H, D_H);
    zero4_kernel<<<(N_NODES / 4 + 255) / 256, 256>>>((float4*)deg, N_NODES / 4);
    hist_kernel<<<edge_blocks, 256>>>(ei, deg);
    scan_kernel<<<1, 1024>>>(deg, offs, cursor);
    fill_kernel<<<edge_blocks, 256>>>(ei, cursor, csr);

    // ---- layer 0 ----
    gather_split<D_IN><<<node_warp_blocks, 256>>>(x, offs, csr, ah, al);
    gemm_mma<false><<<gemm_grid, 256, GEMM_SMEM>>>(ah, al, wh0, wl0, b1_0,
                                                   nullptr, th, tl, N_NODES, D_IN);
    gemm_mma<true ><<<gemm_grid, 256, GEMM_SMEM>>>(th, tl, wh1, wl1, b2_0,
                                                   h, nullptr, nullptr, N_NODES, D_H);

    // ---- layer 1 ----
    gather_split<D_H><<<node_warp_blocks, 256>>>(h, offs, csr, ah, al);
    gemm_mma<false><<<gemm_grid, 256, GEMM_SMEM>>>(ah, al, wh2, wl2, b1_1,
                                                   nullptr, th, tl, N_NODES, D_H);
    gemm_mma<true ><<<gemm_grid, 256, GEMM_SMEM>>>(th, tl, wh3, wl3, b2_1,
                                                   h, nullptr, nullptr, N_NODES, D_H);

    // ---- pool ----
    zero4_kernel<<<(N_GRAPHS * D_H / 4 + 255) / 256, 256>>>((float4*)sums, N_GRAPHS * D_H / 4);
    zero4_kernel<<<1, 32>>>((float4*)counts, N_GRAPHS / 4);
    pool_kernel<<<(N_NODES + POOL_NPB - 1) / POOL_NPB, 256>>>(h, batch, sums, counts);
    div_kernel<<<(N_GRAPHS * D_H + 255) / 256, 256>>>(sums, counts, out);
}

// round 6
// speedup vs baseline: 2.5029x; 1.0702x over previous
#include <cuda_runtime.h>
#include <cuda_bf16.h>
#include <cstdint>

#define N_NODES  50000
#define N_EDGES  800000
#define N_GRAPHS 64
#define D_IN     128
#define D_H      256

// ==================== scratch (no allocations allowed) ====================
__device__ float g_h[(size_t)N_NODES * D_H];
__device__ __nv_bfloat16 g_ah[(size_t)N_NODES * D_H];
__device__ __nv_bfloat16 g_al[(size_t)N_NODES * D_H];
__device__ __nv_bfloat16 g_th[(size_t)N_NODES * D_H];
__device__ __nv_bfloat16 g_tl[(size_t)N_NODES * D_H];
__device__ __nv_bfloat16 g_wh[4][D_H * D_H];
__device__ __nv_bfloat16 g_wl[4][D_H * D_H];
__device__ int g_deg[N_NODES];
__device__ int g_offs[N_NODES + 1];
__device__ int g_cursor[N_NODES];
__device__ int g_csr[N_EDGES];
__device__ int g_part[64];
__device__ float g_sums[N_GRAPHS * D_H];
__device__ float g_counts[N_GRAPHS];

__device__ __forceinline__ uint32_t smem_u32(const void* p) {
    uint32_t a;
    asm("{ .reg .u64 t; cvta.to.shared.u64 t, %1; cvt.u32.u64 %0, t; }"
        : "=r"(a) : "l"(p));
    return a;
}

// ==================== small kernels ====================
__global__ void zero4_kernel(float4* __restrict__ p, int n4) {
    int i = blockIdx.x * blockDim.x + threadIdx.x;
    if (i < n4) p[i] = make_float4(0.f, 0.f, 0.f, 0.f);
}

// All 4 weight matrices: fp32 [K][N] -> bf16 hi/lo transposed [N][K], one launch.
__global__ void prep_all_kernel(const float* __restrict__ W0, const float* __restrict__ W1,
                                const float* __restrict__ W2, const float* __restrict__ W3,
                                __nv_bfloat16* __restrict__ wh, __nv_bfloat16* __restrict__ wl) {
    int idx = blockIdx.x * blockDim.x + threadIdx.x;
    const float* W; int K; size_t base; int local;
    if (idx < 128 * 256)           { W = W0; K = 128; base = 0;                local = idx; }
    else if (idx < 128 * 256 + 65536) { W = W1; K = 256; base = (size_t)D_H * D_H;     local = idx - 128 * 256; }
    else if (idx < 128 * 256 + 131072){ W = W2; K = 256; base = (size_t)2 * D_H * D_H; local = idx - 128 * 256 - 65536; }
    else if (idx < 128 * 256 + 196608){ W = W3; K = 256; base = (size_t)3 * D_H * D_H; local = idx - 128 * 256 - 131072; }
    else return;
    int k = local / 256, n = local % 256;
    float w = W[(size_t)k * 256 + n];
    __nv_bfloat16 h = __float2bfloat16(w);
    __nv_bfloat16 l = __float2bfloat16(w - __bfloat162float(h));
    wh[base + (size_t)n * K + k] = h;
    wl[base + (size_t)n * K + k] = l;
}

// ==================== CSR build ====================
__global__ void hist_kernel(const int* __restrict__ ei, int* __restrict__ deg) {
    int e = blockIdx.x * blockDim.x + threadIdx.x;
    if (e < N_EDGES) atomicAdd(&deg[ei[N_EDGES + e]], 1);
}

// Stage 1: per-block (1024) inclusive scan, write to offs[i+1], partial to part[b].
__global__ void scan1_kernel(const int* __restrict__ deg, int* __restrict__ offs,
                             int* __restrict__ part) {
    __shared__ int sw[32];
    int tid = threadIdx.x, b = blockIdx.x;
    int lane = tid & 31, w = tid >> 5;
    int i = b * 1024 + tid;
    int v = (i < N_NODES) ? deg[i] : 0;
    int s = v;
    #pragma unroll
    for (int d = 1; d < 32; d <<= 1) {
        int t = __shfl_up_sync(0xffffffffu, s, d);
        if (lane >= d) s += t;
    }
    if (lane == 31) sw[w] = s;
    __syncthreads();
    if (w == 0) {
        int ss = sw[lane];
        #pragma unroll
        for (int d = 1; d < 32; d <<= 1) {
            int u = __shfl_up_sync(0xffffffffu, ss, d);
            if (lane >= d) ss += u;
        }
        sw[lane] = ss;
    }
    __syncthreads();
    int incl = s + (w > 0 ? sw[w - 1] : 0);
    if (i < N_NODES) offs[i + 1] = incl;
    if (tid == 1023) part[b] = incl;
}

// Stage 2: exclusive scan of <=64 partials, one block.
__global__ void scan2_kernel(int* __restrict__ part, int nb) {
    __shared__ int t[64];
    int tid = threadIdx.x;
    int v = (tid < nb) ? part[tid] : 0;
    t[tid] = v;
    __syncthreads();
    #pragma unroll
    for (int d = 1; d < 64; d <<= 1) {
        int x = (tid >= d) ? t[tid - d] : 0;
        __syncthreads();
        t[tid] += x;
        __syncthreads();
    }
    if (tid < nb) part[tid] = t[tid] - v;   // exclusive
}

// Stage 3: add block offsets, produce cursor = exclusive start per node.
__global__ void scan3_kernel(const int* __restrict__ deg, int* __restrict__ offs,
                             int* __restrict__ cursor, const int* __restrict__ part) {
    int i = blockIdx.x * blockDim.x + threadIdx.x;
    if (i == 0) offs[0] = 0;
    if (i < N_NODES) {
        int val = offs[i + 1] + part[i >> 10];
        offs[i + 1] = val;
        cursor[i] = val - deg[i];
    }
}

__global__ void fill_kernel(const int* __restrict__ ei, int* __restrict__ cursor,
                            int* __restrict__ csr) {
    int e = blockIdx.x * blockDim.x + threadIdx.x;
    if (e < N_EDGES) {
        int pos = atomicAdd(&cursor[ei[N_EDGES + e]], 1);
        csr[pos] = ei[e];
    }
}

// ==================== gather + self-add + bf16 split ====================
template <int F>
__global__ void gather_split(const float* __restrict__ X,
                             const int* __restrict__ offs,
                             const int* __restrict__ csr,
                             __nv_bfloat16* __restrict__ Ah,
                             __nv_bfloat16* __restrict__ Al) {
    int warp = (blockIdx.x * blockDim.x + threadIdx.x) >> 5;
    int lane = threadIdx.x & 31;
    if (warp >= N_NODES) return;
    constexpr int C = F / 128;
    float4 acc[C];
    const float4* xs = (const float4*)(X + (size_t)warp * F);
    #pragma unroll
    for (int c = 0; c < C; c++) acc[c] = xs[lane + c * 32];
    int beg = offs[warp], end = offs[warp + 1];
    for (int e = beg; e < end; e++) {
        int s = csr[e];
        const float4* r = (const float4*)(X + (size_t)s * F);
        #pragma unroll
        for (int c = 0; c < C; c++) {
            float4 v = r[lane + c * 32];
            acc[c].x += v.x; acc[c].y += v.y; acc[c].z += v.z; acc[c].w += v.w;
        }
    }
    #pragma unroll
    for (int c = 0; c < C; c++) {
        float vv[4] = {acc[c].x, acc[c].y, acc[c].z, acc[c].w};
        uint32_t hp[2], lp[2];
        #pragma unroll
        for (int e = 0; e < 2; e++) {
            __nv_bfloat16 h0 = __float2bfloat16(vv[2 * e]);
            __nv_bfloat16 h1 = __float2bfloat16(vv[2 * e + 1]);
            __nv_bfloat16 l0 = __float2bfloat16(vv[2 * e] - __bfloat162float(h0));
            __nv_bfloat16 l1 = __float2bfloat16(vv[2 * e + 1] - __bfloat162float(h1));
            hp[e] = (uint32_t)*(unsigned short*)&h0 | ((uint32_t)*(unsigned short*)&h1 << 16);
            lp[e] = (uint32_t)*(unsigned short*)&l0 | ((uint32_t)*(unsigned short*)&l1 << 16);
        }
        size_t o = (size_t)warp * F + (lane + c * 32) * 4;
        *(uint2*)(Ah + o) = make_uint2(hp[0], hp[1]);
        *(uint2*)(Al + o) = make_uint2(lp[0], lp[1]);
    }
}

// ==================== cp.async double-buffered mma.sync split-GEMM ====================
// C = relu((Ah+Al) @ (Bh+Bl)^T + bias), 3 HMMA terms (hh, hl, lh).
// Block 128x128, 8 warps (4m x 2n), warp tile 32x64, BK=64, 2 LDGSTS stages.
#define GSW 72
#define TILE_B  (128 * GSW * 2)          // one tile, bytes (18432)
#define STAGE_B (4 * TILE_B)             // Ah|Al|Bh|Bl      (73728)
#define GEMM_SMEM (2 * STAGE_B)          // 2 stages         (147456)

__device__ __forceinline__ void mma16816(float* d, const uint32_t* a, const uint32_t* b) {
    asm volatile(
        "mma.sync.aligned.m16n8k16.row.col.f32.bf16.bf16.f32 "
        "{%0,%1,%2,%3}, {%4,%5,%6,%7}, {%8,%9}, {%0,%1,%2,%3};"
        : "+f"(d[0]), "+f"(d[1]), "+f"(d[2]), "+f"(d[3])
        : "r"(a[0]), "r"(a[1]), "r"(a[2]), "r"(a[3]), "r"(b[0]), "r"(b[1]));
}
__device__ __forceinline__ void cp16(uint32_t dst, const void* src, int srcsize) {
    asm volatile("cp.async.cg.shared.global [%0], [%1], 16, %2;"
                 :: "r"(dst), "l"(src), "r"(srcsize) : "memory");
}

template <bool OUT_F32>
__global__ void __launch_bounds__(256, 1)
gemm_mma(const __nv_bfloat16* __restrict__ Ahg, const __nv_bfloat16* __restrict__ Alg,
         const __nv_bfloat16* __restrict__ BhT, const __nv_bfloat16* __restrict__ BlT,
         const float* __restrict__ bias,
         float* __restrict__ Cf, __nv_bfloat16* __restrict__ Ch,
         __nv_bfloat16* __restrict__ Cl, int M, int K) {
    extern __shared__ char smem_raw[];
    const uint32_t sb = smem_u32(smem_raw);

    const int tid  = threadIdx.x;
    const int wid  = tid >> 5;
    const int lane = tid & 31;
    const int m0   = blockIdx.x * 128;
    const int n0   = blockIdx.y * 128;
    const int wm   = (wid & 3) * 32;
    const int wn   = (wid >> 2) * 64;
    const int fr   = lane >> 2;
    const int fc   = (lane & 3) * 2;

    // per-thread load coords (4 chunks of 16B per tile)
    const int lrow[4] = { (tid + 0)   >> 3, (tid + 256) >> 3,
                          (tid + 512) >> 3, (tid + 768) >> 3 };
    const int lq = tid & 7;

    float acc[2][8][4];
    #pragma unroll
    for (int a = 0; a < 2; a++)
        #pragma unroll
        for (int b = 0; b < 8; b++)
            #pragma unroll
            for (int c = 0; c < 4; c++) acc[a][b][c] = 0.f;

    const int niter = K >> 6;

    auto issue = [&](int it, int stg) {
        const uint32_t sab = sb + stg * STAGE_B;
        const int k0 = it * 64;
        #pragma unroll
        for (int t = 0; t < 4; t++) {
            int row = lrow[t];
            uint32_t so = (uint32_t)(row * GSW + lq * 8) * 2;
            int gm = m0 + row;
            int pm = (gm < M) ? 16 : 0;
            int gma = (gm < M) ? gm : 0;
            const __nv_bfloat16* pa = Ahg + (size_t)gma * K + k0 + lq * 8;
            const __nv_bfloat16* pl = Alg + (size_t)gma * K + k0 + lq * 8;
            cp16(sab + 0 * TILE_B + so, pa, pm);
            cp16(sab + 1 * TILE_B + so, pl, pm);
            const __nv_bfloat16* pbh = BhT + (size_t)(n0 + row) * K + k0 + lq * 8;
            const __nv_bfloat16* pbl = BlT + (size_t)(n0 + row) * K + k0 + lq * 8;
            cp16(sab + 2 * TILE_B + so, pbh, 16);
            cp16(sab + 3 * TILE_B + so, pbl, 16);
        }
        asm volatile("cp.async.commit_group;" ::: "memory");
    };

    issue(0, 0);
    for (int it = 0; it < niter; it++) {
        int stg = it & 1;
        if (it + 1 < niter) {
            issue(it + 1, stg ^ 1);
            asm volatile("cp.async.wait_group 1;" ::: "memory");
        } else {
            asm volatile("cp.async.wait_group 0;" ::: "memory");
        }
        __syncthreads();

        const __nv_bfloat16* sAh = (const __nv_bfloat16*)(smem_raw + stg * STAGE_B);
        const __nv_bfloat16* sAl = (const __nv_bfloat16*)(smem_raw + stg * STAGE_B + TILE_B);
        const __nv_bfloat16* sBh = (const __nv_bfloat16*)(smem_raw + stg * STAGE_B + 2 * TILE_B);
        const __nv_bfloat16* sBl = (const __nv_bfloat16*)(smem_raw + stg * STAGE_B + 3 * TILE_B);

        #pragma unroll
        for (int kk = 0; kk < 64; kk += 16) {
            uint32_t ah[2][4], al[2][4];
            #pragma unroll
            for (int mt = 0; mt < 2; mt++) {
                int base = wm + mt * 16;
                int o0 = (base + fr) * GSW + kk + fc;
                int o1 = (base + fr + 8) * GSW + kk + fc;
                ah[mt][0] = *(const uint32_t*)(sAh + o0);
                ah[mt][1] = *(const uint32_t*)(sAh + o1);
                ah[mt][2] = *(const uint32_t*)(sAh + o0 + 8);
                ah[mt][3] = *(const uint32_t*)(sAh + o1 + 8);
                al[mt][0] = *(const uint32_t*)(sAl + o0);
                al[mt][1] = *(const uint32_t*)(sAl + o1);
                al[mt][2] = *(const uint32_t*)(sAl + o0 + 8);
                al[mt][3] = *(const uint32_t*)(sAl + o1 + 8);
            }
            #pragma unroll
            for (int nt = 0; nt < 8; nt++) {
                int ob = (wn + nt * 8 + fr) * GSW + kk + fc;
                uint32_t bh[2], bl[2];
                bh[0] = *(const uint32_t*)(sBh + ob);
                bh[1] = *(const uint32_t*)(sBh + ob + 8);
                bl[0] = *(const uint32_t*)(sBl + ob);
                bl[1] = *(const uint32_t*)(sBl + ob + 8);
                #pragma unroll
                for (int mt = 0; mt < 2; mt++) {
                    mma16816(acc[mt][nt], ah[mt], bh);
                    mma16816(acc[mt][nt], ah[mt], bl);
                    mma16816(acc[mt][nt], al[mt], bh);
                }
            }
        }
        __syncthreads();
    }

    // ---- epilogue: bias + relu ----
    #pragma unroll
    for (int mt = 0; mt < 2; mt++) {
        int gr0 = m0 + wm + mt * 16 + fr;
        int gr1 = gr0 + 8;
        #pragma unroll
        for (int nt = 0; nt < 8; nt++) {
            int col = n0 + wn + nt * 8 + fc;
            float b0 = bias[col], b1 = bias[col + 1];
            float v00 = fmaxf(acc[mt][nt][0] + b0, 0.f);
            float v01 = fmaxf(acc[mt][nt][1] + b1, 0.f);
            float v10 = fmaxf(acc[mt][nt][2] + b0, 0.f);
            float v11 = fmaxf(acc[mt][nt][3] + b1, 0.f);
            if (OUT_F32) {
                if (gr0 < M) *(float2*)(Cf + (size_t)gr0 * 256 + col) = make_float2(v00, v01);
                if (gr1 < M) *(float2*)(Cf + (size_t)gr1 * 256 + col) = make_float2(v10, v11);
            } else {
                if (gr0 < M) {
                    __nv_bfloat16 h0 = __float2bfloat16(v00), h1 = __float2bfloat16(v01);
                    __nv_bfloat16 l0 = __float2bfloat16(v00 - __bfloat162float(h0));
                    __nv_bfloat16 l1 = __float2bfloat16(v01 - __bfloat162float(h1));
                    *(uint32_t*)(Ch + (size_t)gr0 * 256 + col) =
                        (uint32_t)*(unsigned short*)&h0 | ((uint32_t)*(unsigned short*)&h1 << 16);
                    *(uint32_t*)(Cl + (size_t)gr0 * 256 + col) =
                        (uint32_t)*(unsigned short*)&l0 | ((uint32_t)*(unsigned short*)&l1 << 16);
                }
                if (gr1 < M) {
                    __nv_bfloat16 h0 = __float2bfloat16(v10), h1 = __float2bfloat16(v11);
                    __nv_bfloat16 l0 = __float2bfloat16(v10 - __bfloat162float(h0));
                    __nv_bfloat16 l1 = __float2bfloat16(v11 - __bfloat162float(h1));
                    *(uint32_t*)(Ch + (size_t)gr1 * 256 + col) =
                        (uint32_t)*(unsigned short*)&h0 | ((uint32_t)*(unsigned short*)&h1 << 16);
                    *(uint32_t*)(Cl + (size_t)gr1 * 256 + col) =
                        (uint32_t)*(unsigned short*)&l0 | ((uint32_t)*(unsigned short*)&l1 << 16);
                }
            }
        }
    }
}

// ==================== pool ====================
#define POOL_NPB 128
__global__ void pool_kernel(const float* __restrict__ H,
                            const int* __restrict__ batch,
                            float* __restrict__ sums, float* __restrict__ counts) {
    int f  = threadIdx.x;
    int n0 = blockIdx.x * POOL_NPB;
    int n1 = n0 + POOL_NPB;
    if (n1 > N_NODES) n1 = N_NODES;
    if (n0 >= N_NODES) return;

    float acc = 0.f;
    int cur = batch[n0];
    int runstart = n0;
    for (int n = n0; n < n1; n++) {
        int g = batch[n];
        if (g != cur) {
            atomicAdd(&sums[cur * D_H + f], acc);
            if (f == 0) atomicAdd(&counts[cur], (float)(n - runstart));
            acc = 0.f; cur = g; runstart = n;
        }
        acc += H[(size_t)n * D_H + f];
    }
    atomicAdd(&sums[cur * D_H + f], acc);
    if (f == 0) atomicAdd(&counts[cur], (float)(n1 - runstart));
}

__global__ void div_kernel(const float* __restrict__ sums,
                           const float* __restrict__ counts,
                           float* __restrict__ out) {
    int i = blockIdx.x * blockDim.x + threadIdx.x;
    if (i < N_GRAPHS * D_H) out[i] = sums[i] / fmaxf(counts[i >> 8], 1.f);
}

// ==================== launch ====================
extern "C" void kernel_launch(void* const* d_in, const int* in_sizes, int n_in,
                              void* d_out, int out_size) {
    const float* x     = (const float*)d_in[0];
    const int*   ei    = (const int*)d_in[1];
    const int*   batch = (const int*)d_in[2];
    const float* W1_0 = (const float*)d_in[3];
    const float* b1_0 = (const float*)d_in[4];
    const float* W2_0 = (const float*)d_in[5];
    const float* b2_0 = (const float*)d_in[6];
    const float* W1_1 = (const float*)d_in[7];
    const float* b1_1 = (const float*)d_in[8];
    const float* W2_1 = (const float*)d_in[9];
    const float* b2_1 = (const float*)d_in[10];
    float* out = (float*)d_out;

    float *h, *sums, *counts;
    __nv_bfloat16 *ah, *al, *th, *tl, *wh, *wl;
    int *deg, *offs, *cursor, *csr, *part;
    cudaGetSymbolAddress((void**)&h,      g_h);
    cudaGetSymbolAddress((void**)&ah,     g_ah);
    cudaGetSymbolAddress((void**)&al,     g_al);
    cudaGetSymbolAddress((void**)&th,     g_th);
    cudaGetSymbolAddress((void**)&tl,     g_tl);
    cudaGetSymbolAddress((void**)&wh,     g_wh);
    cudaGetSymbolAddress((void**)&wl,     g_wl);
    cudaGetSymbolAddress((void**)&deg,    g_deg);
    cudaGetSymbolAddress((void**)&offs,   g_offs);
    cudaGetSymbolAddress((void**)&cursor, g_cursor);
    cudaGetSymbolAddress((void**)&csr,    g_csr);
    cudaGetSymbolAddress((void**)&part,   g_part);
    cudaGetSymbolAddress((void**)&sums,   g_sums);
    cudaGetSymbolAddress((void**)&counts, g_counts);
    __nv_bfloat16* wh0 = wh;                 __nv_bfloat16* wl0 = wl;
    __nv_bfloat16* wh1 = wh + D_H * D_H;     __nv_bfloat16* wl1 = wl + D_H * D_H;
    __nv_bfloat16* wh2 = wh + 2 * D_H * D_H; __nv_bfloat16* wl2 = wl + 2 * D_H * D_H;
    __nv_bfloat16* wh3 = wh + 3 * D_H * D_H; __nv_bfloat16* wl3 = wl + 3 * D_H * D_H;

    cudaFuncSetAttribute(gemm_mma<false>, cudaFuncAttributeMaxDynamicSharedMemorySize, GEMM_SMEM);
    cudaFuncSetAttribute(gemm_mma<true >, cudaFuncAttributeMaxDynamicSharedMemorySize, GEMM_SMEM);

    const dim3 gemm_grid((N_NODES + 127) / 128, 2);
    const int  edge_blocks = (N_EDGES + 255) / 256;
    const int  node_warp_blocks = (N_NODES * 32 + 255) / 256;
    const int  scan_blocks = (N_NODES + 1023) / 1024;

    // ---- prep + CSR build ----
    prep_all_kernel<<<(128 * 256 + 3 * 65536 + 255) / 256, 256>>>(W1_0, W2_0, W1_1, W2_1, wh, wl);
    zero4_kernel<<<(N_NODES / 4 + 255) / 256, 256>>>((float4*)deg, N_NODES / 4);
    hist_kernel<<<edge_blocks, 256>>>(ei, deg);
    scan1_kernel<<<scan_blocks, 1024>>>(deg, offs, part);
    scan2_kernel<<<1, 64>>>(part, scan_blocks);
    scan3_kernel<<<(N_NODES + 255) / 256, 256>>>(deg, offs, cursor, part);
    fill_kernel<<<edge_blocks, 256>>>(ei, cursor, csr);

    // ---- layer 0 ----
    gather_split<D_IN><<<node_warp_blocks, 256>>>(x, offs, csr, ah, al);
    gemm_mma<false><<<gemm_grid, 256, GEMM_SMEM>>>(ah, al, wh0, wl0, b1_0,
                                                   nullptr, th, tl, N_NODES, D_IN);
    gemm_mma<true ><<<gemm_grid, 256, GEMM_SMEM>>>(th, tl, wh1, wl1, b2_0,
                                                   h, nullptr, nullptr, N_NODES, D_H);

    // ---- layer 1 ----
    gather_split<D_H><<<node_warp_blocks, 256>>>(h, offs, csr, ah, al);
    gemm_mma<false><<<gemm_grid, 256, GEMM_SMEM>>>(ah, al, wh2, wl2, b1_1,
                                                   nullptr, th, tl, N_NODES, D_H);
    gemm_mma<true ><<<gemm_grid, 256, GEMM_SMEM>>>(th, tl, wh3, wl3, b2_1,
                                                   h, nullptr, nullptr, N_NODES, D_H);

    // ---- pool ----
    zero4_kernel<<<(N_GRAPHS * D_H / 4 + 255) / 256, 256>>>((float4*)sums, N_GRAPHS * D_H / 4);
    zero4_kernel<<<1, 32>>>((float4*)counts, N_GRAPHS / 4);
    pool_kernel<<<(N_NODES + POOL_NPB - 1) / POOL_NPB, 256>>>(h, batch, sums, counts);
    div_kernel<<<(N_GRAPHS * D_H + 255) / 256, 256>>>(sums, counts, out);
}

// round 7
// speedup vs baseline: 3.5824x; 1.4313x over previous
#include <cuda_runtime.h>
#include <cuda_fp16.h>
#include <cstdint>

#define N_NODES  50000
#define N_EDGES  800000
#define N_GRAPHS 64
#define D_IN     128
#define D_H      256

// ==================== scratch (no allocations allowed) ====================
__device__ __half g_x16[(size_t)N_NODES * D_IN];
__device__ __half g_a16[(size_t)N_NODES * D_H];
__device__ __half g_t16[(size_t)N_NODES * D_H];
__device__ __half g_h16[(size_t)N_NODES * D_H];
__device__ __half g_wh[4][D_H * D_H];
__device__ __half g_wl[4][D_H * D_H];
__device__ int g_deg[N_NODES];
__device__ int g_offs[N_NODES + 1];
__device__ int g_cursor[N_NODES];
__device__ int g_csr[N_EDGES];
__device__ int g_part[64];
__device__ float g_sums[N_GRAPHS * D_H];
__device__ float g_counts[N_GRAPHS];

__device__ __forceinline__ uint32_t smem_u32(const void* p) {
    uint32_t a;
    asm("{ .reg .u64 t; cvta.to.shared.u64 t, %1; cvt.u32.u64 %0, t; }"
        : "=r"(a) : "l"(p));
    return a;
}

// ==================== small kernels ====================
__global__ void zero4_kernel(float4* __restrict__ p, int n4) {
    int i = blockIdx.x * blockDim.x + threadIdx.x;
    if (i < n4) p[i] = make_float4(0.f, 0.f, 0.f, 0.f);
}

__global__ void zero_pool_kernel(float* __restrict__ sums, float* __restrict__ counts) {
    int i = blockIdx.x * blockDim.x + threadIdx.x;
    if (i < N_GRAPHS * D_H) sums[i] = 0.f;
    else if (i < N_GRAPHS * D_H + N_GRAPHS) counts[i - N_GRAPHS * D_H] = 0.f;
}

// x fp32 -> fp16
__global__ void cvt_x_kernel(const float4* __restrict__ x, uint2* __restrict__ x16, int n4) {
    int i = blockIdx.x * blockDim.x + threadIdx.x;
    if (i >= n4) return;
    float4 v = x[i];
    __half2 a = __floats2half2_rn(v.x, v.y);
    __half2 b = __floats2half2_rn(v.z, v.w);
    x16[i] = make_uint2(*(uint32_t*)&a, *(uint32_t*)&b);
}

// All 4 weight matrices: fp32 [K][256] -> fp16 hi/lo transposed [256][K], one launch.
__global__ void prep_all_kernel(const float* __restrict__ W0, const float* __restrict__ W1,
                                const float* __restrict__ W2, const float* __restrict__ W3,
                                __half* __restrict__ wh, __half* __restrict__ wl) {
    int idx = blockIdx.x * blockDim.x + threadIdx.x;
    const float* W; int K; size_t base; int local;
    if (idx < 128 * 256)              { W = W0; K = 128; base = 0;                     local = idx; }
    else if (idx < 128 * 256 + 65536) { W = W1; K = 256; base = (size_t)D_H * D_H;     local = idx - 128 * 256; }
    else if (idx < 128 * 256 + 131072){ W = W2; K = 256; base = (size_t)2 * D_H * D_H; local = idx - 128 * 256 - 65536; }
    else if (idx < 128 * 256 + 196608){ W = W3; K = 256; base = (size_t)3 * D_H * D_H; local = idx - 128 * 256 - 131072; }
    else return;
    int k = local / 256, n = local % 256;
    float w = W[(size_t)k * 256 + n];
    __half h = __float2half_rn(w);
    __half l = __float2half_rn(w - __half2float(h));
    wh[base + (size_t)n * K + k] = h;
    wl[base + (size_t)n * K + k] = l;
}

// ==================== CSR build ====================
__global__ void hist_kernel(const int* __restrict__ ei, int* __restrict__ deg) {
    int e = blockIdx.x * blockDim.x + threadIdx.x;
    if (e < N_EDGES) atomicAdd(&deg[ei[N_EDGES + e]], 1);
}

__global__ void scan1_kernel(const int* __restrict__ deg, int* __restrict__ offs,
                             int* __restrict__ part) {
    __shared__ int sw[32];
    int tid = threadIdx.x, b = blockIdx.x;
    int lane = tid & 31, w = tid >> 5;
    int i = b * 1024 + tid;
    int v = (i < N_NODES) ? deg[i] : 0;
    int s = v;
    #pragma unroll
    for (int d = 1; d < 32; d <<= 1) {
        int t = __shfl_up_sync(0xffffffffu, s, d);
        if (lane >= d) s += t;
    }
    if (lane == 31) sw[w] = s;
    __syncthreads();
    if (w == 0) {
        int ss = sw[lane];
        #pragma unroll
        for (int d = 1; d < 32; d <<= 1) {
            int u = __shfl_up_sync(0xffffffffu, ss, d);
            if (lane >= d) ss += u;
        }
        sw[lane] = ss;
    }
    __syncthreads();
    int incl = s + (w > 0 ? sw[w - 1] : 0);
    if (i < N_NODES) offs[i + 1] = incl;
    if (tid == 1023) part[b] = incl;
}

__global__ void scan2_kernel(int* __restrict__ part, int nb) {
    __shared__ int t[64];
    int tid = threadIdx.x;
    int v = (tid < nb) ? part[tid] : 0;
    t[tid] = v;
    __syncthreads();
    #pragma unroll
    for (int d = 1; d < 64; d <<= 1) {
        int x = (tid >= d) ? t[tid - d] : 0;
        __syncthreads();
        t[tid] += x;
        __syncthreads();
    }
    if (tid < nb) part[tid] = t[tid] - v;
}

__global__ void scan3_kernel(const int* __restrict__ deg, int* __restrict__ offs,
                             int* __restrict__ cursor, const int* __restrict__ part) {
    int i = blockIdx.x * blockDim.x + threadIdx.x;
    if (i == 0) offs[0] = 0;
    if (i < N_NODES) {
        int val = offs[i + 1] + part[i >> 10];
        offs[i + 1] = val;
        cursor[i] = val - deg[i];
    }
}

__global__ void fill_kernel(const int* __restrict__ ei, int* __restrict__ cursor,
                            int* __restrict__ csr) {
    int e = blockIdx.x * blockDim.x + threadIdx.x;
    if (e < N_EDGES) {
        int pos = atomicAdd(&cursor[ei[N_EDGES + e]], 1);
        csr[pos] = ei[e];
    }
}

// ==================== fp16 gather: A[n] = X[n] + sum_{s in nbrs(n)} X[s] ====================
// One warp per node; fp32 accumulation; fp16 in/out. F floats-per-row (128 or 256).
template <int F>
__global__ void gather_f16(const __half* __restrict__ X,
                           const int* __restrict__ offs,
                           const int* __restrict__ csr,
                           __half* __restrict__ A) {
    int warp = (blockIdx.x * blockDim.x + threadIdx.x) >> 5;
    int lane = threadIdx.x & 31;
    if (warp >= N_NODES) return;
    constexpr int C = F / 128;          // uint2 (4 halves) chunks per lane
    float2 acc[C][2];
    const uint2* xs = (const uint2*)(X + (size_t)warp * F);
    #pragma unroll
    for (int c = 0; c < C; c++) {
        uint2 v = xs[lane + c * 32];
        acc[c][0] = __half22float2(*(__half2*)&v.x);
        acc[c][1] = __half22float2(*(__half2*)&v.y);
    }
    int beg = offs[warp], end = offs[warp + 1];
    for (int e = beg; e < end; e++) {
        int s = csr[e];
        const uint2* r = (const uint2*)(X + (size_t)s * F);
        #pragma unroll
        for (int c = 0; c < C; c++) {
            uint2 v = r[lane + c * 32];
            float2 f0 = __half22float2(*(__half2*)&v.x);
            float2 f1 = __half22float2(*(__half2*)&v.y);
            acc[c][0].x += f0.x; acc[c][0].y += f0.y;
            acc[c][1].x += f1.x; acc[c][1].y += f1.y;
        }
    }
    uint2* out = (uint2*)(A + (size_t)warp * F);
    #pragma unroll
    for (int c = 0; c < C; c++) {
        __half2 o0 = __floats2half2_rn(acc[c][0].x, acc[c][0].y);
        __half2 o1 = __floats2half2_rn(acc[c][1].x, acc[c][1].y);
        out[lane + c * 32] = make_uint2(*(uint32_t*)&o0, *(uint32_t*)&o1);
    }
}

// ==================== cp.async double-buffered fp16 2-term mma GEMM ====================
// C = relu(A @ (Bh+Bl)^T + bias), A single fp16, 2 HMMA terms per logical MMA.
// Block 128x128, 8 warps (4m x 2n), warp tile 32x64, BK=64, 2 LDGSTS stages.
#define GSW 72
#define TILE_B  (128 * GSW * 2)               // 18432 B
#define STAGE_B (3 * TILE_B)                  // A | Bh | Bl  (55296)
#define GEMM_SMEM (2 * STAGE_B)               // 110592

__device__ __forceinline__ void mma_f16(float* d, const uint32_t* a, const uint32_t* b) {
    asm volatile(
        "mma.sync.aligned.m16n8k16.row.col.f32.f16.f16.f32 "
        "{%0,%1,%2,%3}, {%4,%5,%6,%7}, {%8,%9}, {%0,%1,%2,%3};"
        : "+f"(d[0]), "+f"(d[1]), "+f"(d[2]), "+f"(d[3])
        : "r"(a[0]), "r"(a[1]), "r"(a[2]), "r"(a[3]), "r"(b[0]), "r"(b[1]));
}
__device__ __forceinline__ void cp16(uint32_t dst, const void* src, int srcsize) {
    asm volatile("cp.async.cg.shared.global [%0], [%1], 16, %2;"
                 :: "r"(dst), "l"(src), "r"(srcsize) : "memory");
}

__global__ void __launch_bounds__(256, 2)
gemm_f16(const __half* __restrict__ Ag,
         const __half* __restrict__ BhT, const __half* __restrict__ BlT,
         const float* __restrict__ bias,
         __half* __restrict__ O, int M, int K) {
    extern __shared__ char smem_raw[];
    const uint32_t sb = smem_u32(smem_raw);

    const int tid  = threadIdx.x;
    const int wid  = tid >> 5;
    const int lane = tid & 31;
    const int m0   = blockIdx.x * 128;
    const int n0   = blockIdx.y * 128;
    const int wm   = (wid & 3) * 32;
    const int wn   = (wid >> 2) * 64;
    const int fr   = lane >> 2;
    const int fc   = (lane & 3) * 2;

    const int lrow[4] = { (tid + 0)   >> 3, (tid + 256) >> 3,
                          (tid + 512) >> 3, (tid + 768) >> 3 };
    const int lq = tid & 7;

    float acc[2][8][4];
    #pragma unroll
    for (int a = 0; a < 2; a++)
        #pragma unroll
        for (int b = 0; b < 8; b++)
            #pragma unroll
            for (int c = 0; c < 4; c++) acc[a][b][c] = 0.f;

    const int niter = K >> 6;

    auto issue = [&](int it, int stg) {
        const uint32_t sab = sb + stg * STAGE_B;
        const int k0 = it * 64;
        #pragma unroll
        for (int t = 0; t < 4; t++) {
            int row = lrow[t];
            uint32_t so = (uint32_t)(row * GSW + lq * 8) * 2;
            int gm = m0 + row;
            int pm = (gm < M) ? 16 : 0;
            int gma = (gm < M) ? gm : 0;
            cp16(sab + 0 * TILE_B + so, Ag  + (size_t)gma * K + k0 + lq * 8, pm);
            cp16(sab + 1 * TILE_B + so, BhT + (size_t)(n0 + row) * K + k0 + lq * 8, 16);
            cp16(sab + 2 * TILE_B + so, BlT + (size_t)(n0 + row) * K + k0 + lq * 8, 16);
        }
        asm volatile("cp.async.commit_group;" ::: "memory");
    };

    issue(0, 0);
    for (int it = 0; it < niter; it++) {
        int stg = it & 1;
        if (it + 1 < niter) {
            issue(it + 1, stg ^ 1);
            asm volatile("cp.async.wait_group 1;" ::: "memory");
        } else {
            asm volatile("cp.async.wait_group 0;" ::: "memory");
        }
        __syncthreads();

        const __half* sA  = (const __half*)(smem_raw + stg * STAGE_B);
        const __half* sBh = (const __half*)(smem_raw + stg * STAGE_B + TILE_B);
        const __half* sBl = (const __half*)(smem_raw + stg * STAGE_B + 2 * TILE_B);

        #pragma unroll
        for (int kk = 0; kk < 64; kk += 16) {
            uint32_t af[2][4];
            #pragma unroll
            for (int mt = 0; mt < 2; mt++) {
                int base = wm + mt * 16;
                int o0 = (base + fr) * GSW + kk + fc;
                int o1 = (base + fr + 8) * GSW + kk + fc;
                af[mt][0] = *(const uint32_t*)(sA + o0);
                af[mt][1] = *(const uint32_t*)(sA + o1);
                af[mt][2] = *(const uint32_t*)(sA + o0 + 8);
                af[mt][3] = *(const uint32_t*)(sA + o1 + 8);
            }
            #pragma unroll
            for (int nt = 0; nt < 8; nt++) {
                int ob = (wn + nt * 8 + fr) * GSW + kk + fc;
                uint32_t bh[2], bl[2];
                bh[0] = *(const uint32_t*)(sBh + ob);
                bh[1] = *(const uint32_t*)(sBh + ob + 8);
                bl[0] = *(const uint32_t*)(sBl + ob);
                bl[1] = *(const uint32_t*)(sBl + ob + 8);
                #pragma unroll
                for (int mt = 0; mt < 2; mt++) {
                    mma_f16(acc[mt][nt], af[mt], bh);
                    mma_f16(acc[mt][nt], af[mt], bl);
                }
            }
        }
        __syncthreads();
    }

    // ---- epilogue: bias + relu -> fp16 ----
    #pragma unroll
    for (int mt = 0; mt < 2; mt++) {
        int gr0 = m0 + wm + mt * 16 + fr;
        int gr1 = gr0 + 8;
        #pragma unroll
        for (int nt = 0; nt < 8; nt++) {
            int col = n0 + wn + nt * 8 + fc;
            float b0 = bias[col], b1 = bias[col + 1];
            if (gr0 < M) {
                __half2 p = __floats2half2_rn(fmaxf(acc[mt][nt][0] + b0, 0.f),
                                              fmaxf(acc[mt][nt][1] + b1, 0.f));
                *(__half2*)(O + (size_t)gr0 * 256 + col) = p;
            }
            if (gr1 < M) {
                __half2 p = __floats2half2_rn(fmaxf(acc[mt][nt][2] + b0, 0.f),
                                              fmaxf(acc[mt][nt][3] + b1, 0.f));
                *(__half2*)(O + (size_t)gr1 * 256 + col) = p;
            }
        }
    }
}

// ==================== pool (fp16 in, fp32 out) ====================
#define POOL_NPB 128
__global__ void pool_kernel(const __half* __restrict__ H,
                            const int* __restrict__ batch,
                            float* __restrict__ sums, float* __restrict__ counts) {
    int f  = threadIdx.x;
    int n0 = blockIdx.x * POOL_NPB;
    int n1 = n0 + POOL_NPB;
    if (n1 > N_NODES) n1 = N_NODES;
    if (n0 >= N_NODES) return;

    float acc = 0.f;
    int cur = batch[n0];
    int runstart = n0;
    for (int n = n0; n < n1; n++) {
        int g = batch[n];
        if (g != cur) {
            atomicAdd(&sums[cur * D_H + f], acc);
            if (f == 0) atomicAdd(&counts[cur], (float)(n - runstart));
            acc = 0.f; cur = g; runstart = n;
        }
        acc += __half2float(H[(size_t)n * D_H + f]);
    }
    atomicAdd(&sums[cur * D_H + f], acc);
    if (f == 0) atomicAdd(&counts[cur], (float)(n1 - runstart));
}

__global__ void div_kernel(const float* __restrict__ sums,
                           const float* __restrict__ counts,
                           float* __restrict__ out) {
    int i = blockIdx.x * blockDim.x + threadIdx.x;
    if (i < N_GRAPHS * D_H) out[i] = sums[i] / fmaxf(counts[i >> 8], 1.f);
}

// ==================== launch ====================
extern "C" void kernel_launch(void* const* d_in, const int* in_sizes, int n_in,
                              void* d_out, int out_size) {
    const float* x     = (const float*)d_in[0];
    const int*   ei    = (const int*)d_in[1];
    const int*   batch = (const int*)d_in[2];
    const float* W1_0 = (const float*)d_in[3];
    const float* b1_0 = (const float*)d_in[4];
    const float* W2_0 = (const float*)d_in[5];
    const float* b2_0 = (const float*)d_in[6];
    const float* W1_1 = (const float*)d_in[7];
    const float* b1_1 = (const float*)d_in[8];
    const float* W2_1 = (const float*)d_in[9];
    const float* b2_1 = (const float*)d_in[10];
    float* out = (float*)d_out;

    float *sums, *counts;
    __half *x16, *a16, *t16, *h16, *wh, *wl;
    int *deg, *offs, *cursor, *csr, *part;
    cudaGetSymbolAddress((void**)&x16,    g_x16);
    cudaGetSymbolAddress((void**)&a16,    g_a16);
    cudaGetSymbolAddress((void**)&t16,    g_t16);
    cudaGetSymbolAddress((void**)&h16,    g_h16);
    cudaGetSymbolAddress((void**)&wh,     g_wh);
    cudaGetSymbolAddress((void**)&wl,     g_wl);
    cudaGetSymbolAddress((void**)&deg,    g_deg);
    cudaGetSymbolAddress((void**)&offs,   g_offs);
    cudaGetSymbolAddress((void**)&cursor, g_cursor);
    cudaGetSymbolAddress((void**)&csr,    g_csr);
    cudaGetSymbolAddress((void**)&part,   g_part);
    cudaGetSymbolAddress((void**)&sums,   g_sums);
    cudaGetSymbolAddress((void**)&counts, g_counts);
    __half* wh0 = wh;                 __half* wl0 = wl;
    __half* wh1 = wh + D_H * D_H;     __half* wl1 = wl + D_H * D_H;
    __half* wh2 = wh + 2 * D_H * D_H; __half* wl2 = wl + 2 * D_H * D_H;
    __half* wh3 = wh + 3 * D_H * D_H; __half* wl3 = wl + 3 * D_H * D_H;

    cudaFuncSetAttribute(gemm_f16, cudaFuncAttributeMaxDynamicSharedMemorySize, GEMM_SMEM);

    const dim3 gemm_grid((N_NODES + 127) / 128, 2);
    const int  edge_blocks = (N_EDGES + 255) / 256;
    const int  node_warp_blocks = (N_NODES * 32 + 255) / 256;
    const int  scan_blocks = (N_NODES + 1023) / 1024;

    // ---- prep + CSR build ----
    prep_all_kernel<<<(128 * 256 + 3 * 65536 + 255) / 256, 256>>>(W1_0, W2_0, W1_1, W2_1, wh, wl);
    cvt_x_kernel<<<(N_NODES * D_IN / 4 + 255) / 256, 256>>>((const float4*)x, (uint2*)x16,
                                                            N_NODES * D_IN / 4);
    zero4_kernel<<<(N_NODES / 4 + 255) / 256, 256>>>((float4*)deg, N_NODES / 4);
    hist_kernel<<<edge_blocks, 256>>>(ei, deg);
    scan1_kernel<<<scan_blocks, 1024>>>(deg, offs, part);
    scan2_kernel<<<1, 64>>>(part, scan_blocks);
    scan3_kernel<<<(N_NODES + 255) / 256, 256>>>(deg, offs, cursor, part);
    fill_kernel<<<edge_blocks, 256>>>(ei, cursor, csr);

    // ---- layer 0 ----
    gather_f16<D_IN><<<node_warp_blocks, 256>>>(x16, offs, csr, a16);
    gemm_f16<<<gemm_grid, 256, GEMM_SMEM>>>(a16, wh0, wl0, b1_0, t16, N_NODES, D_IN);
    gemm_f16<<<gemm_grid, 256, GEMM_SMEM>>>(t16, wh1, wl1, b2_0, h16, N_NODES, D_H);

    // ---- layer 1 ----
    gather_f16<D_H><<<node_warp_blocks, 256>>>(h16, offs, csr, a16);
    gemm_f16<<<gemm_grid, 256, GEMM_SMEM>>>(a16, wh2, wl2, b1_1, t16, N_NODES, D_H);
    gemm_f16<<<gemm_grid, 256, GEMM_SMEM>>>(t16, wh3, wl3, b2_1, h16, N_NODES, D_H);

    // ---- pool ----
    zero_pool_kernel<<<(N_GRAPHS * D_H + N_GRAPHS + 255) / 256, 256>>>(sums, counts);
    pool_kernel<<<(N_NODES + POOL_NPB - 1) / POOL_NPB, 256>>>(h16, batch, sums, counts);
    div_kernel<<<(N_GRAPHS * D_H + 255) / 256, 256>>>(sums, counts, out);
}

// round 8
// speedup vs baseline: 4.5318x; 1.2650x over previous
#include <cuda_runtime.h>
#include <cuda_fp16.h>
#include <cstdint>

#define N_NODES  50000
#define N_EDGES  800000
#define N_GRAPHS 64
#define D_IN     128
#define D_H      256

// ==================== scratch (no allocations allowed) ====================
__device__ __half g_a16[(size_t)N_NODES * D_H];
__device__ __half g_t16[(size_t)N_NODES * D_H];
__device__ __half g_h16[(size_t)N_NODES * D_H];
__device__ __half g_wh[4][D_H * D_H];
__device__ int g_deg[N_NODES];
__device__ int g_offs[N_NODES + 1];
__device__ int g_cursor[N_NODES];
__device__ int g_csr[N_EDGES];
__device__ int g_part[64];
__device__ float g_sums[N_GRAPHS * D_H];
__device__ float g_counts[N_GRAPHS];

__device__ __forceinline__ uint32_t smem_u32(const void* p) {
    uint32_t a;
    asm("{ .reg .u64 t; cvta.to.shared.u64 t, %1; cvt.u32.u64 %0, t; }"
        : "=r"(a) : "l"(p));
    return a;
}

// ==================== small kernels ====================
__global__ void zero4_kernel(float4* __restrict__ p, int n4) {
    int i = blockIdx.x * blockDim.x + threadIdx.x;
    if (i < n4) p[i] = make_float4(0.f, 0.f, 0.f, 0.f);
}

__global__ void zero_pool_kernel(float* __restrict__ sums, float* __restrict__ counts) {
    int i = blockIdx.x * blockDim.x + threadIdx.x;
    if (i < N_GRAPHS * D_H) sums[i] = 0.f;
    else if (i < N_GRAPHS * D_H + N_GRAPHS) counts[i - N_GRAPHS * D_H] = 0.f;
}

// All 4 weight matrices: fp32 [K][256] -> fp16 transposed [256][K], one launch.
__global__ void prep_all_kernel(const float* __restrict__ W0, const float* __restrict__ W1,
                                const float* __restrict__ W2, const float* __restrict__ W3,
                                __half* __restrict__ wh) {
    int idx = blockIdx.x * blockDim.x + threadIdx.x;
    const float* W; int K; size_t base; int local;
    if (idx < 128 * 256)              { W = W0; K = 128; base = 0;                     local = idx; }
    else if (idx < 128 * 256 + 65536) { W = W1; K = 256; base = (size_t)D_H * D_H;     local = idx - 128 * 256; }
    else if (idx < 128 * 256 + 131072){ W = W2; K = 256; base = (size_t)2 * D_H * D_H; local = idx - 128 * 256 - 65536; }
    else if (idx < 128 * 256 + 196608){ W = W3; K = 256; base = (size_t)3 * D_H * D_H; local = idx - 128 * 256 - 131072; }
    else return;
    int k = local / 256, n = local % 256;
    wh[base + (size_t)n * K + k] = __float2half_rn(W[(size_t)k * 256 + n]);
}

// ==================== CSR build ====================
__global__ void hist_kernel(const int* __restrict__ ei, int* __restrict__ deg) {
    int e = blockIdx.x * blockDim.x + threadIdx.x;
    if (e < N_EDGES) atomicAdd(&deg[ei[N_EDGES + e]], 1);
}

__global__ void scan1_kernel(const int* __restrict__ deg, int* __restrict__ offs,
                             int* __restrict__ part) {
    __shared__ int sw[32];
    int tid = threadIdx.x, b = blockIdx.x;
    int lane = tid & 31, w = tid >> 5;
    int i = b * 1024 + tid;
    int v = (i < N_NODES) ? deg[i] : 0;
    int s = v;
    #pragma unroll
    for (int d = 1; d < 32; d <<= 1) {
        int t = __shfl_up_sync(0xffffffffu, s, d);
        if (lane >= d) s += t;
    }
    if (lane == 31) sw[w] = s;
    __syncthreads();
    if (w == 0) {
        int ss = sw[lane];
        #pragma unroll
        for (int d = 1; d < 32; d <<= 1) {
            int u = __shfl_up_sync(0xffffffffu, ss, d);
            if (lane >= d) ss += u;
        }
        sw[lane] = ss;
    }
    __syncthreads();
    int incl = s + (w > 0 ? sw[w - 1] : 0);
    if (i < N_NODES) offs[i + 1] = incl;
    if (tid == 1023) part[b] = incl;
}

__global__ void scan2_kernel(int* __restrict__ part, int nb) {
    __shared__ int t[64];
    int tid = threadIdx.x;
    int v = (tid < nb) ? part[tid] : 0;
    t[tid] = v;
    __syncthreads();
    #pragma unroll
    for (int d = 1; d < 64; d <<= 1) {
        int x = (tid >= d) ? t[tid - d] : 0;
        __syncthreads();
        t[tid] += x;
        __syncthreads();
    }
    if (tid < nb) part[tid] = t[tid] - v;
}

__global__ void scan3_kernel(const int* __restrict__ deg, int* __restrict__ offs,
                             int* __restrict__ cursor, const int* __restrict__ part) {
    int i = blockIdx.x * blockDim.x + threadIdx.x;
    if (i == 0) offs[0] = 0;
    if (i < N_NODES) {
        int val = offs[i + 1] + part[i >> 10];
        offs[i + 1] = val;
        cursor[i] = val - deg[i];
    }
}

__global__ void fill_kernel(const int* __restrict__ ei, int* __restrict__ cursor,
                            int* __restrict__ csr) {
    int e = blockIdx.x * blockDim.x + threadIdx.x;
    if (e < N_EDGES) {
        int pos = atomicAdd(&cursor[ei[N_EDGES + e]], 1);
        csr[pos] = ei[e];
    }
}

// ==================== gather: A[n] = X[n] + sum_{s in nbrs(n)} X[s] -> fp16 ====================
// One warp per node; fp32 accumulation. IN_F32: X is fp32 (layer 0), else fp16.
template <int F, bool IN_F32>
__global__ void gather_any(const void* __restrict__ Xv,
                           const int* __restrict__ offs,
                           const int* __restrict__ csr,
                           __half* __restrict__ A) {
    int warp = (blockIdx.x * blockDim.x + threadIdx.x) >> 5;
    int lane = threadIdx.x & 31;
    if (warp >= N_NODES) return;
    constexpr int C = F / 128;          // 4-element chunks per lane
    float acc[C][4];

    if (IN_F32) {
        const float* X = (const float*)Xv;
        const float4* xs = (const float4*)(X + (size_t)warp * F);
        #pragma unroll
        for (int c = 0; c < C; c++) {
            float4 v = xs[lane + c * 32];
            acc[c][0] = v.x; acc[c][1] = v.y; acc[c][2] = v.z; acc[c][3] = v.w;
        }
        int beg = offs[warp], end = offs[warp + 1];
        for (int e = beg; e < end; e++) {
            const float4* r = (const float4*)(X + (size_t)csr[e] * F);
            #pragma unroll
            for (int c = 0; c < C; c++) {
                float4 v = r[lane + c * 32];
                acc[c][0] += v.x; acc[c][1] += v.y; acc[c][2] += v.z; acc[c][3] += v.w;
            }
        }
    } else {
        const __half* X = (const __half*)Xv;
        const uint2* xs = (const uint2*)(X + (size_t)warp * F);
        #pragma unroll
        for (int c = 0; c < C; c++) {
            uint2 v = xs[lane + c * 32];
            float2 f0 = __half22float2(*(__half2*)&v.x);
            float2 f1 = __half22float2(*(__half2*)&v.y);
            acc[c][0] = f0.x; acc[c][1] = f0.y; acc[c][2] = f1.x; acc[c][3] = f1.y;
        }
        int beg = offs[warp], end = offs[warp + 1];
        for (int e = beg; e < end; e++) {
            const uint2* r = (const uint2*)(X + (size_t)csr[e] * F);
            #pragma unroll
            for (int c = 0; c < C; c++) {
                uint2 v = r[lane + c * 32];
                float2 f0 = __half22float2(*(__half2*)&v.x);
                float2 f1 = __half22float2(*(__half2*)&v.y);
                acc[c][0] += f0.x; acc[c][1] += f0.y; acc[c][2] += f1.x; acc[c][3] += f1.y;
            }
        }
    }

    uint2* out = (uint2*)(A + (size_t)warp * F);
    #pragma unroll
    for (int c = 0; c < C; c++) {
        __half2 o0 = __floats2half2_rn(acc[c][0], acc[c][1]);
        __half2 o1 = __floats2half2_rn(acc[c][2], acc[c][3]);
        out[lane + c * 32] = make_uint2(*(uint32_t*)&o0, *(uint32_t*)&o1);
    }
}

// ==================== cp.async double-buffered fp16 mma GEMM (single term) ====================
// C = relu(A @ B^T + bias).  Block 128x128, 8 warps (4m x 2n), warp 32x64, BK=64.
#define GSW 72
#define TILE_B  (128 * GSW * 2)               // 18432 B
#define STAGE_B (2 * TILE_B)                  // A | B  (36864)
#define GEMM_SMEM (2 * STAGE_B)               // 73728

__device__ __forceinline__ void mma_f16(float* d, const uint32_t* a, const uint32_t* b) {
    asm volatile(
        "mma.sync.aligned.m16n8k16.row.col.f32.f16.f16.f32 "
        "{%0,%1,%2,%3}, {%4,%5,%6,%7}, {%8,%9}, {%0,%1,%2,%3};"
        : "+f"(d[0]), "+f"(d[1]), "+f"(d[2]), "+f"(d[3])
        : "r"(a[0]), "r"(a[1]), "r"(a[2]), "r"(a[3]), "r"(b[0]), "r"(b[1]));
}
__device__ __forceinline__ void cp16(uint32_t dst, const void* src, int srcsize) {
    asm volatile("cp.async.cg.shared.global [%0], [%1], 16, %2;"
                 :: "r"(dst), "l"(src), "r"(srcsize) : "memory");
}

__global__ void __launch_bounds__(256, 2)
gemm_f16(const __half* __restrict__ Ag, const __half* __restrict__ BT,
         const float* __restrict__ bias,
         __half* __restrict__ O, int M, int K) {
    extern __shared__ char smem_raw[];
    const uint32_t sb = smem_u32(smem_raw);

    const int tid  = threadIdx.x;
    const int wid  = tid >> 5;
    const int lane = tid & 31;
    const int m0   = blockIdx.x * 128;
    const int n0   = blockIdx.y * 128;
    const int wm   = (wid & 3) * 32;
    const int wn   = (wid >> 2) * 64;
    const int fr   = lane >> 2;
    const int fc   = (lane & 3) * 2;

    const int lrow[4] = { (tid + 0)   >> 3, (tid + 256) >> 3,
                          (tid + 512) >> 3, (tid + 768) >> 3 };
    const int lq = tid & 7;

    float acc[2][8][4];
    #pragma unroll
    for (int a = 0; a < 2; a++)
        #pragma unroll
        for (int b = 0; b < 8; b++)
            #pragma unroll
            for (int c = 0; c < 4; c++) acc[a][b][c] = 0.f;

    const int niter = K >> 6;

    auto issue = [&](int it, int stg) {
        const uint32_t sab = sb + stg * STAGE_B;
        const int k0 = it * 64;
        #pragma unroll
        for (int t = 0; t < 4; t++) {
            int row = lrow[t];
            uint32_t so = (uint32_t)(row * GSW + lq * 8) * 2;
            int gm = m0 + row;
            int pm = (gm < M) ? 16 : 0;
            int gma = (gm < M) ? gm : 0;
            cp16(sab + 0 * TILE_B + so, Ag + (size_t)gma * K + k0 + lq * 8, pm);
            cp16(sab + 1 * TILE_B + so, BT + (size_t)(n0 + row) * K + k0 + lq * 8, 16);
        }
        asm volatile("cp.async.commit_group;" ::: "memory");
    };

    issue(0, 0);
    for (int it = 0; it < niter; it++) {
        int stg = it & 1;
        if (it + 1 < niter) {
            issue(it + 1, stg ^ 1);
            asm volatile("cp.async.wait_group 1;" ::: "memory");
        } else {
            asm volatile("cp.async.wait_group 0;" ::: "memory");
        }
        __syncthreads();

        const __half* sA = (const __half*)(smem_raw + stg * STAGE_B);
        const __half* sB = (const __half*)(smem_raw + stg * STAGE_B + TILE_B);

        #pragma unroll
        for (int kk = 0; kk < 64; kk += 16) {
            uint32_t af[2][4];
            #pragma unroll
            for (int mt = 0; mt < 2; mt++) {
                int base = wm + mt * 16;
                int o0 = (base + fr) * GSW + kk + fc;
                int o1 = (base + fr + 8) * GSW + kk + fc;
                af[mt][0] = *(const uint32_t*)(sA + o0);
                af[mt][1] = *(const uint32_t*)(sA + o1);
                af[mt][2] = *(const uint32_t*)(sA + o0 + 8);
                af[mt][3] = *(const uint32_t*)(sA + o1 + 8);
            }
            #pragma unroll
            for (int nt = 0; nt < 8; nt++) {
                int ob = (wn + nt * 8 + fr) * GSW + kk + fc;
                uint32_t bf[2];
                bf[0] = *(const uint32_t*)(sB + ob);
                bf[1] = *(const uint32_t*)(sB + ob + 8);
                #pragma unroll
                for (int mt = 0; mt < 2; mt++)
                    mma_f16(acc[mt][nt], af[mt], bf);
            }
        }
        __syncthreads();
    }

    // ---- epilogue: bias + relu -> fp16 ----
    #pragma unroll
    for (int mt = 0; mt < 2; mt++) {
        int gr0 = m0 + wm + mt * 16 + fr;
        int gr1 = gr0 + 8;
        #pragma unroll
        for (int nt = 0; nt < 8; nt++) {
            int col = n0 + wn + nt * 8 + fc;
            float b0 = bias[col], b1 = bias[col + 1];
            if (gr0 < M) {
                __half2 p = __floats2half2_rn(fmaxf(acc[mt][nt][0] + b0, 0.f),
                                              fmaxf(acc[mt][nt][1] + b1, 0.f));
                *(__half2*)(O + (size_t)gr0 * 256 + col) = p;
            }
            if (gr1 < M) {
                __half2 p = __floats2half2_rn(fmaxf(acc[mt][nt][2] + b0, 0.f),
                                              fmaxf(acc[mt][nt][3] + b1, 0.f));
                *(__half2*)(O + (size_t)gr1 * 256 + col) = p;
            }
        }
    }
}

// ==================== pool (fp16 in, fp32 out) ====================
#define POOL_NPB 128
__global__ void pool_kernel(const __half* __restrict__ H,
                            const int* __restrict__ batch,
                            float* __restrict__ sums, float* __restrict__ counts) {
    int f  = threadIdx.x;
    int n0 = blockIdx.x * POOL_NPB;
    int n1 = n0 + POOL_NPB;
    if (n1 > N_NODES) n1 = N_NODES;
    if (n0 >= N_NODES) return;

    float acc = 0.f;
    int cur = batch[n0];
    int runstart = n0;
    for (int n = n0; n < n1; n++) {
        int g = batch[n];
        if (g != cur) {
            atomicAdd(&sums[cur * D_H + f], acc);
            if (f == 0) atomicAdd(&counts[cur], (float)(n - runstart));
            acc = 0.f; cur = g; runstart = n;
        }
        acc += __half2float(H[(size_t)n * D_H + f]);
    }
    atomicAdd(&sums[cur * D_H + f], acc);
    if (f == 0) atomicAdd(&counts[cur], (float)(n1 - runstart));
}

__global__ void div_kernel(const float* __restrict__ sums,
                           const float* __restrict__ counts,
                           float* __restrict__ out) {
    int i = blockIdx.x * blockDim.x + threadIdx.x;
    if (i < N_GRAPHS * D_H) out[i] = sums[i] / fmaxf(counts[i >> 8], 1.f);
}

// ==================== launch ====================
extern "C" void kernel_launch(void* const* d_in, const int* in_sizes, int n_in,
                              void* d_out, int out_size) {
    const float* x     = (const float*)d_in[0];
    const int*   ei    = (const int*)d_in[1];
    const int*   batch = (const int*)d_in[2];
    const float* W1_0 = (const float*)d_in[3];
    const float* b1_0 = (const float*)d_in[4];
    const float* W2_0 = (const float*)d_in[5];
    const float* b2_0 = (const float*)d_in[6];
    const float* W1_1 = (const float*)d_in[7];
    const float* b1_1 = (const float*)d_in[8];
    const float* W2_1 = (const float*)d_in[9];
    const float* b2_1 = (const float*)d_in[10];
    float* out = (float*)d_out;

    float *sums, *counts;
    __half *a16, *t16, *h16, *wh;
    int *deg, *offs, *cursor, *csr, *part;
    cudaGetSymbolAddress((void**)&a16,    g_a16);
    cudaGetSymbolAddress((void**)&t16,    g_t16);
    cudaGetSymbolAddress((void**)&h16,    g_h16);
    cudaGetSymbolAddress((void**)&wh,     g_wh);
    cudaGetSymbolAddress((void**)&deg,    g_deg);
    cudaGetSymbolAddress((void**)&offs,   g_offs);
    cudaGetSymbolAddress((void**)&cursor, g_cursor);
    cudaGetSymbolAddress((void**)&csr,    g_csr);
    cudaGetSymbolAddress((void**)&part,   g_part);
    cudaGetSymbolAddress((void**)&sums,   g_sums);
    cudaGetSymbolAddress((void**)&counts, g_counts);
    __half* wh0 = wh;
    __half* wh1 = wh + D_H * D_H;
    __half* wh2 = wh + 2 * D_H * D_H;
    __half* wh3 = wh + 3 * D_H * D_H;

    cudaFuncSetAttribute(gemm_f16, cudaFuncAttributeMaxDynamicSharedMemorySize, GEMM_SMEM);

    const dim3 gemm_grid((N_NODES + 127) / 128, 2);
    const int  edge_blocks = (N_EDGES + 255) / 256;
    const int  node_warp_blocks = (N_NODES * 32 + 255) / 256;
    const int  scan_blocks = (N_NODES + 1023) / 1024;

    // ---- prep + CSR build ----
    prep_all_kernel<<<(128 * 256 + 3 * 65536 + 255) / 256, 256>>>(W1_0, W2_0, W1_1, W2_1, wh);
    zero4_kernel<<<(N_NODES / 4 + 255) / 256, 256>>>((float4*)deg, N_NODES / 4);
    hist_kernel<<<edge_blocks, 256>>>(ei, deg);
    scan1_kernel<<<scan_blocks, 1024>>>(deg, offs, part);
    scan2_kernel<<<1, 64>>>(part, scan_blocks);
    scan3_kernel<<<(N_NODES + 255) / 256, 256>>>(deg, offs, cursor, part);
    fill_kernel<<<edge_blocks, 256>>>(ei, cursor, csr);

    // ---- layer 0 ----
    gather_any<D_IN, true><<<node_warp_blocks, 256>>>(x, offs, csr, a16);
    gemm_f16<<<gemm_grid, 256, GEMM_SMEM>>>(a16, wh0, b1_0, t16, N_NODES, D_IN);
    gemm_f16<<<gemm_grid, 256, GEMM_SMEM>>>(t16, wh1, b2_0, h16, N_NODES, D_H);

    // ---- layer 1 ----
    gather_any<D_H, false><<<node_warp_blocks, 256>>>(h16, offs, csr, a16);
    gemm_f16<<<gemm_grid, 256, GEMM_SMEM>>>(a16, wh2, b1_1, t16, N_NODES, D_H);
    gemm_f16<<<gemm_grid, 256, GEMM_SMEM>>>(t16, wh3, b2_1, h16, N_NODES, D_H);

    // ---- pool ----
    zero_pool_kernel<<<(N_GRAPHS * D_H + N_GRAPHS + 255) / 256, 256>>>(sums, counts);
    pool_kernel<<<(N_NODES + POOL_NPB - 1) / POOL_NPB, 256>>>(h16, batch, sums, counts);
    div_kernel<<<(N_GRAPHS * D_H + 255) / 256, 256>>>(sums, counts, out);
}